// round 12
// baseline (speedup 1.0000x reference)
#include <cuda_runtime.h>
#include <cuda_fp16.h>
#include <math.h>
#include <stdint.h>

// ---------------- problem constants ----------------
#define TT    16384
#define CC    512
#define C3    1536
#define HID   2048
#define NHEAD 8
#define HDIM  64
#define SEQ   256
#define NSEQ  64

typedef unsigned long long u64;

// ---------------- scratch ----------------
__device__ __half g_h1h [(size_t)TT * CC];    // ln1 out (fp16)
__device__ float  g_qkv [(size_t)TT * C3];    // qkv (fp32, attention needs precision)
__device__ __half g_oh  [(size_t)TT * CC];    // attention out (fp16)
__device__ float  g_x1  [(size_t)TT * CC];    // x + proj (fp32, residual)
__device__ __half g_h2h [(size_t)TT * CC];    // ln2 out (fp16)
__device__ __half g_ffh [(size_t)TT * HID];   // ffn hidden (fp16)
__device__ __half g_wqkvh [(size_t)C3 * CC];  // weights, fp16-converted once
__device__ __half g_wprojh[(size_t)CC * CC];
__device__ __half g_w1h   [(size_t)HID * CC];
__device__ __half g_w2h   [(size_t)CC * HID];

// ---------------- f32x2 helpers (attention) ----------------
static __device__ __forceinline__ u64 pack2(float lo, float hi) {
    u64 r; asm("mov.b64 %0,{%1,%2};" : "=l"(r) : "f"(lo), "f"(hi)); return r;
}
static __device__ __forceinline__ float2 unpack2(u64 v) {
    float2 r; asm("mov.b64 {%0,%1},%2;" : "=f"(r.x), "=f"(r.y) : "l"(v)); return r;
}
static __device__ __forceinline__ u64 fma2(u64 a, u64 b, u64 c) {
    u64 d; asm("fma.rn.f32x2 %0,%1,%2,%3;" : "=l"(d) : "l"(a), "l"(b), "l"(c)); return d;
}
static __device__ __forceinline__ u64 mul2(u64 a, u64 b) {
    u64 d; asm("mul.rn.f32x2 %0,%1,%2;" : "=l"(d) : "l"(a), "l"(b)); return d;
}

// ---------------- mma.sync / ldmatrix helpers (sm_80+ PTX) ----------------
static __device__ __forceinline__ uint32_t smem_u32(const void* p) {
    uint32_t a;
    asm("{ .reg .u64 t; cvta.to.shared.u64 t, %1; cvt.u32.u64 %0, t; }" : "=r"(a) : "l"(p));
    return a;
}
static __device__ __forceinline__ void ldmat_x4(uint32_t* r, uint32_t addr) {
    asm volatile("ldmatrix.sync.aligned.m8n8.x4.shared.b16 {%0,%1,%2,%3}, [%4];"
        : "=r"(r[0]), "=r"(r[1]), "=r"(r[2]), "=r"(r[3]) : "r"(addr));
}
static __device__ __forceinline__ void ldmat_x2(uint32_t* r, uint32_t addr) {
    asm volatile("ldmatrix.sync.aligned.m8n8.x2.shared.b16 {%0,%1}, [%2];"
        : "=r"(r[0]), "=r"(r[1]) : "r"(addr));
}
static __device__ __forceinline__ void mma_f16(float* d, const uint32_t* a, const uint32_t* b) {
    asm volatile("mma.sync.aligned.m16n8k16.row.col.f32.f16.f16.f32 "
        "{%0,%1,%2,%3},{%4,%5,%6,%7},{%8,%9},{%0,%1,%2,%3};"
        : "+f"(d[0]), "+f"(d[1]), "+f"(d[2]), "+f"(d[3])
        : "r"(a[0]), "r"(a[1]), "r"(a[2]), "r"(a[3]), "r"(b[0]), "r"(b[1]));
}
static __device__ __forceinline__ uint32_t h2_u32(__half2 h) {
    union { __half2 h; uint32_t u; } c; c.h = h; return c.u;
}

// ---------------- weight fp32 -> fp16 prep (once per launch) ----------------
__global__ void cvt_h_kernel(const float* __restrict__ in, __half* __restrict__ out) {
    const int i = (blockIdx.x * 256 + threadIdx.x) * 4;
    float4 v = *(const float4*)(in + i);
    __half2 a = __floats2half2_rn(v.x, v.y);
    __half2 b = __floats2half2_rn(v.z, v.w);
    *(uint2*)(out + i) = make_uint2(h2_u32(a), h2_u32(b));
}

// ---------------- pure-fp16 tensor GEMM (NT): C = A[M,K] * B[N,K]^T ---------
// A, B already fp16 in global. Block tile 128x128, 512 threads / 16 warps
// (4x4 grid, 32x32 per warp), K chunk 64, double-buffered smem, no cvt.
#define NTHR   512
#define KCH    64
#define ASTR   144                       // bytes per smem row (64 f16 + 8 pad)
#define TILE_B (128 * ASTR)              // 18432 B
#define BUF_B  (2 * TILE_B)              // A, B = 36864 B
#define GEMM_SMEM (2 * BUF_B)            // 73728 B

// EPI: 0 = plain fp32 out; 1 = fp32 out +bias[n]+res[m,n]; 2 = fp16 out gelu(+bias[n])
template <int EPI>
__global__ void __launch_bounds__(NTHR, 1)
gemm_mma(const __half* __restrict__ A, const __half* __restrict__ B,
         void* __restrict__ Cmat, const float* __restrict__ bias,
         const float* __restrict__ res, int M, int N, int K) {
    extern __shared__ char smem[];
    const uint32_t sb = smem_u32(smem);
    const int tid  = threadIdx.x;
    const int wid  = tid >> 5;
    const int lane = tid & 31;
    const int bm = blockIdx.y << 7;
    const int bn = blockIdx.x << 7;

    const int wm = (wid & 3) * 32;       // warp m-offset
    const int wn = (wid >> 2) * 32;      // warp n-offset

    const uint32_t aro = (uint32_t)(lane & 15) * ASTR + (uint32_t)(lane >> 4) * 16u;
    const uint32_t bro = (uint32_t)(lane & 7) * ASTR + (uint32_t)((lane >> 3) & 1) * 16u;

    float acc[2][4][4];
#pragma unroll
    for (int i = 0; i < 2; i++)
#pragma unroll
        for (int j = 0; j < 4; j++)
#pragma unroll
            for (int e = 0; e < 4; e++) acc[i][j][e] = 0.f;

    const int NC = K / KCH;

    // staging: 128 rows x 64 halves per tile; uint4 = 8 halves; 1024 loads/tile
    // thread does 2 loads per tile: f = i*NTHR + tid; row = f>>3; c8 = (f&7)*8
    // ---- stage chunk 0 into buffer 0 ----
    {
        char* bp = smem;
#pragma unroll
        for (int i = 0; i < 2; i++) {
            int f = i * NTHR + tid;
            int row = f >> 3, c8 = (f & 7) << 3;
            uint4 v = *(const uint4*)(A + (size_t)(bm + row) * K + c8);
            *(uint4*)(bp + (uint32_t)row * ASTR + (uint32_t)c8 * 2u) = v;
        }
#pragma unroll
        for (int i = 0; i < 2; i++) {
            int f = i * NTHR + tid;
            int row = f >> 3, c8 = (f & 7) << 3;
            uint4 v = *(const uint4*)(B + (size_t)(bn + row) * K + c8);
            *(uint4*)(bp + TILE_B + (uint32_t)row * ASTR + (uint32_t)c8 * 2u) = v;
        }
    }
    __syncthreads();

    for (int c = 0; c < NC; ++c) {
        // ---- prefetch chunk c+1 into other buffer ----
        if (c + 1 < NC) {
            char* bp = smem + ((c + 1) & 1) * BUF_B;
            const int kb = (c + 1) * KCH;
#pragma unroll
            for (int i = 0; i < 2; i++) {
                int f = i * NTHR + tid;
                int row = f >> 3, c8 = (f & 7) << 3;
                uint4 v = *(const uint4*)(A + (size_t)(bm + row) * K + kb + c8);
                *(uint4*)(bp + (uint32_t)row * ASTR + (uint32_t)c8 * 2u) = v;
            }
#pragma unroll
            for (int i = 0; i < 2; i++) {
                int f = i * NTHR + tid;
                int row = f >> 3, c8 = (f & 7) << 3;
                uint4 v = *(const uint4*)(B + (size_t)(bn + row) * K + kb + c8);
                *(uint4*)(bp + TILE_B + (uint32_t)row * ASTR + (uint32_t)c8 * 2u) = v;
            }
        }

        // ---- compute chunk c ----
        const uint32_t bufb = sb + (c & 1) * BUF_B;
        const uint32_t aT = bufb, bT = bufb + TILE_B;

#pragma unroll
        for (int ks = 0; ks < 4; ks++) {
            const uint32_t kso = (uint32_t)ks * 32u;
            uint32_t bh[4][2];
#pragma unroll
            for (int nt = 0; nt < 4; nt++) {
                const uint32_t ro = (uint32_t)(wn + nt * 8) * ASTR + kso + bro;
                ldmat_x2(bh[nt], bT + ro);
            }
            uint32_t ah[2][4];
#pragma unroll
            for (int mt = 0; mt < 2; mt++) {
                const uint32_t ro = (uint32_t)(wm + mt * 16) * ASTR + kso + aro;
                ldmat_x4(ah[mt], aT + ro);
            }
#pragma unroll
            for (int mt = 0; mt < 2; mt++)
#pragma unroll
                for (int nt = 0; nt < 4; nt++)
                    mma_f16(acc[mt][nt], ah[mt], bh[nt]);
        }
        __syncthreads();
    }

    // ---- epilogue from register fragments ----
    const int g   = lane >> 2;
    const int tig = lane & 3;
#pragma unroll
    for (int mt = 0; mt < 2; mt++) {
#pragma unroll
        for (int half = 0; half < 2; half++) {
            const int m = bm + wm + mt * 16 + g + 8 * half;
            const float* rrow = (EPI == 1) ? (res + (size_t)m * N) : nullptr;
#pragma unroll
            for (int nt = 0; nt < 4; nt++) {
                const int cb = bn + wn + nt * 8 + 2 * tig;
                float v0 = acc[mt][nt][2 * half];
                float v1 = acc[mt][nt][2 * half + 1];
                if (EPI == 1) {
                    float2 rv = *(const float2*)(rrow + cb);
                    v0 += bias[cb] + rv.x;
                    v1 += bias[cb + 1] + rv.y;
                    float2 ov = { v0, v1 };
                    *(float2*)((float*)Cmat + (size_t)m * N + cb) = ov;
                } else if (EPI == 2) {
                    float t0 = v0 + bias[cb], t1 = v1 + bias[cb + 1];
                    v0 = 0.5f * t0 * (1.0f + erff(t0 * 0.70710678118654752f));
                    v1 = 0.5f * t1 * (1.0f + erff(t1 * 0.70710678118654752f));
                    __half2 hv = __floats2half2_rn(v0, v1);
                    *(__half2*)((__half*)Cmat + (size_t)m * N + cb) = hv;
                } else {
                    float2 ov = { v0, v1 };
                    *(float2*)((float*)Cmat + (size_t)m * N + cb) = ov;
                }
            }
        }
    }
}

// ---------------- LayerNorm: one warp per token, fp16 out ----------------
__global__ void ln_kernel(const float* __restrict__ x, const float* __restrict__ g,
                          const float* __restrict__ b, __half* __restrict__ out) {
    const int warp = (blockIdx.x * 256 + threadIdx.x) >> 5;
    const int lane = threadIdx.x & 31;
    const float4* row = (const float4*)(x + (size_t)warp * CC);
    float4 v[4];
    float s = 0.f, q = 0.f;
#pragma unroll
    for (int i = 0; i < 4; i++) {
        v[i] = row[lane + 32 * i];
        s += v[i].x + v[i].y + v[i].z + v[i].w;
        q += v[i].x * v[i].x + v[i].y * v[i].y + v[i].z * v[i].z + v[i].w * v[i].w;
    }
#pragma unroll
    for (int o = 16; o; o >>= 1) {
        s += __shfl_xor_sync(0xFFFFFFFFu, s, o);
        q += __shfl_xor_sync(0xFFFFFFFFu, q, o);
    }
    const float mu  = s * (1.0f / CC);
    const float var = fmaxf(q * (1.0f / CC) - mu * mu, 0.0f);
    const float r   = rsqrtf(var + 1e-5f);

    __half* orow = out + (size_t)warp * CC;
    const float4* gg = (const float4*)g;
    const float4* bb = (const float4*)b;
#pragma unroll
    for (int i = 0; i < 4; i++) {
        float4 gv = gg[lane + 32 * i], bv = bb[lane + 32 * i];
        float o0 = (v[i].x - mu) * r * gv.x + bv.x;
        float o1 = (v[i].y - mu) * r * gv.y + bv.y;
        float o2 = (v[i].z - mu) * r * gv.z + bv.z;
        float o3 = (v[i].w - mu) * r * gv.w + bv.w;
        __half2 a = __floats2half2_rn(o0, o1);
        __half2 c = __floats2half2_rn(o2, o3);
        *(uint2*)(orow + (lane + 32 * i) * 4) = make_uint2(h2_u32(a), h2_u32(c));
    }
}

// ---------------- Attention: fp32 compute, fp16 out ----------------
__global__ void __launch_bounds__(256, 1)
attn_kernel(const float* __restrict__ qkv, __half* __restrict__ o) {
    __shared__ float Ks[64 * 64];
    __shared__ float Vs[64 * 64];
    const int head = blockIdx.x;
    const int seqb = blockIdx.y * SEQ;
    const int tid  = threadIdx.x;
    const int tq   = seqb + tid;

    u64 q2[32], o2[32];
    {
        const float4* qp = (const float4*)(qkv + (size_t)tq * C3 + head * HDIM);
#pragma unroll
        for (int t = 0; t < 16; t++) {
            float4 v = qp[t];
            q2[2 * t]     = pack2(v.x * 0.125f, v.y * 0.125f);
            q2[2 * t + 1] = pack2(v.z * 0.125f, v.w * 0.125f);
            o2[2 * t] = 0ull; o2[2 * t + 1] = 0ull;
        }
    }
    float mx = -1e30f, sm = 0.f;

    for (int ck = 0; ck < 4; ++ck) {
        __syncthreads();
#pragma unroll
        for (int it = 0; it < 4; ++it) {
            const int idx = it * 256 + tid;
            const int r = idx >> 4, c4 = idx & 15;
            const float* base = qkv + (size_t)(seqb + ck * 64 + r) * C3 + head * HDIM + c4 * 4;
            ((float4*)Ks)[idx] = *(const float4*)(base + 512);
            ((float4*)Vs)[idx] = *(const float4*)(base + 1024);
        }
        __syncthreads();

        for (int m = 0; m < 64; m++) {
            const u64* K2 = (const u64*)(Ks + m * 64);
            u64 s4[4] = { 0ull, 0ull, 0ull, 0ull };
#pragma unroll
            for (int j = 0; j < 32; j += 4) {
                s4[0] = fma2(q2[j + 0], K2[j + 0], s4[0]);
                s4[1] = fma2(q2[j + 1], K2[j + 1], s4[1]);
                s4[2] = fma2(q2[j + 2], K2[j + 2], s4[2]);
                s4[3] = fma2(q2[j + 3], K2[j + 3], s4[3]);
            }
            float2 p0 = unpack2(s4[0]), p1 = unpack2(s4[1]);
            float2 p2 = unpack2(s4[2]), p3 = unpack2(s4[3]);
            const float s = ((p0.x + p0.y) + (p1.x + p1.y)) + ((p2.x + p2.y) + (p3.x + p3.y));

            const float mn   = fmaxf(mx, s);
            const float corr = __expf(mx - mn);
            const float p    = __expf(s - mn);
            sm = sm * corr + p;
            mx = mn;

            const u64 cd = pack2(corr, corr);
            const u64 pd = pack2(p, p);
            const u64* V2 = (const u64*)(Vs + m * 64);
#pragma unroll
            for (int j = 0; j < 32; j++)
                o2[j] = fma2(o2[j], cd, mul2(pd, V2[j]));
        }
    }

    const float inv = 1.0f / sm;
    __half* op = o + (size_t)tq * CC + head * HDIM;
#pragma unroll
    for (int t = 0; t < 16; t++) {
        float2 a = unpack2(o2[2 * t]);
        float2 b = unpack2(o2[2 * t + 1]);
        __half2 h0 = __floats2half2_rn(a.x * inv, a.y * inv);
        __half2 h1 = __floats2half2_rn(b.x * inv, b.y * inv);
        *(uint2*)(op + t * 4) = make_uint2(h2_u32(h0), h2_u32(h1));
    }
}

// ---------------- launcher ----------------
extern "C" void kernel_launch(void* const* d_in, const int* in_sizes, int n_in,
                              void* d_out, int out_size) {
    const float* x     = (const float*)d_in[0];
    const float* ln1g  = (const float*)d_in[1];
    const float* ln1b  = (const float*)d_in[2];
    const float* wqkv  = (const float*)d_in[3];
    const float* wproj = (const float*)d_in[4];
    const float* bproj = (const float*)d_in[5];
    const float* ln2g  = (const float*)d_in[6];
    const float* ln2b  = (const float*)d_in[7];
    const float* w1    = (const float*)d_in[8];
    const float* b1    = (const float*)d_in[9];
    const float* w2    = (const float*)d_in[10];
    const float* b2    = (const float*)d_in[11];
    float* out = (float*)d_out;

    __half *h1h, *oh, *h2h, *ffh, *wqkvh, *wprojh, *w1h, *w2h;
    float *qkv, *x1;
    cudaGetSymbolAddress((void**)&h1h,   g_h1h);
    cudaGetSymbolAddress((void**)&qkv,   g_qkv);
    cudaGetSymbolAddress((void**)&oh,    g_oh);
    cudaGetSymbolAddress((void**)&x1,    g_x1);
    cudaGetSymbolAddress((void**)&h2h,   g_h2h);
    cudaGetSymbolAddress((void**)&ffh,   g_ffh);
    cudaGetSymbolAddress((void**)&wqkvh, g_wqkvh);
    cudaGetSymbolAddress((void**)&wprojh,g_wprojh);
    cudaGetSymbolAddress((void**)&w1h,   g_w1h);
    cudaGetSymbolAddress((void**)&w2h,   g_w2h);

    cudaFuncSetAttribute(gemm_mma<0>, cudaFuncAttributeMaxDynamicSharedMemorySize, GEMM_SMEM);
    cudaFuncSetAttribute(gemm_mma<1>, cudaFuncAttributeMaxDynamicSharedMemorySize, GEMM_SMEM);
    cudaFuncSetAttribute(gemm_mma<2>, cudaFuncAttributeMaxDynamicSharedMemorySize, GEMM_SMEM);

    // 0) weight fp32 -> fp16 (once per launch; tiny)
    cvt_h_kernel<<<(C3 * CC) / 1024, 256>>>(wqkv, wqkvh);
    cvt_h_kernel<<<(CC * CC) / 1024, 256>>>(wproj, wprojh);
    cvt_h_kernel<<<(HID * CC) / 1024, 256>>>(w1, w1h);
    cvt_h_kernel<<<(CC * HID) / 1024, 256>>>(w2, w2h);

    // 1) LN1 (fp16 out)
    ln_kernel<<<TT / 8, 256>>>(x, ln1g, ln1b, h1h);
    // 2) QKV = h1 @ w_qkv^T (fp32 out)
    gemm_mma<0><<<dim3(C3 / 128, TT / 128), NTHR, GEMM_SMEM>>>(h1h, wqkvh, qkv, nullptr, nullptr, TT, C3, CC);
    // 3) attention (fp16 out)
    attn_kernel<<<dim3(NHEAD, NSEQ), 256>>>(qkv, oh);
    // 4) x1 = x + o @ w_proj^T + b_proj (fp32 out)
    gemm_mma<1><<<dim3(CC / 128, TT / 128), NTHR, GEMM_SMEM>>>(oh, wprojh, x1, bproj, x, TT, CC, CC);
    // 5) LN2 (fp16 out)
    ln_kernel<<<TT / 8, 256>>>(x1, ln2g, ln2b, h2h);
    // 6) ff = gelu(h2 @ w1^T + b1) (fp16 out)
    gemm_mma<2><<<dim3(HID / 128, TT / 128), NTHR, GEMM_SMEM>>>(h2h, w1h, ffh, b1, nullptr, TT, HID, CC);
    // 7) out = x1 + ff @ w2^T + b2 (fp32 out)
    gemm_mma<1><<<dim3(CC / 128, TT / 128), NTHR, GEMM_SMEM>>>(ffh, w2h, out, b2, x1, TT, CC, HID);
}

// round 13
// speedup vs baseline: 1.3992x; 1.3992x over previous
#include <cuda_runtime.h>
#include <cuda_fp16.h>
#include <math.h>
#include <stdint.h>

// ---------------- problem constants ----------------
#define TT    16384
#define CC    512
#define C3    1536
#define HID   2048
#define NHEAD 8
#define HDIM  64
#define SEQ   256
#define NSEQ  64

typedef unsigned long long u64;

// ---------------- scratch ----------------
__device__ float g_h1 [(size_t)TT * CC];
__device__ float g_qkv[(size_t)TT * C3];
__device__ float g_o  [(size_t)TT * CC];
__device__ float g_x1 [(size_t)TT * CC];
__device__ float g_h2 [(size_t)TT * CC];
__device__ float g_ff [(size_t)TT * HID];

// ---------------- f32x2 helpers (attention) ----------------
static __device__ __forceinline__ u64 pack2(float lo, float hi) {
    u64 r; asm("mov.b64 %0,{%1,%2};" : "=l"(r) : "f"(lo), "f"(hi)); return r;
}
static __device__ __forceinline__ float2 unpack2(u64 v) {
    float2 r; asm("mov.b64 {%0,%1},%2;" : "=f"(r.x), "=f"(r.y) : "l"(v)); return r;
}
static __device__ __forceinline__ u64 fma2(u64 a, u64 b, u64 c) {
    u64 d; asm("fma.rn.f32x2 %0,%1,%2,%3;" : "=l"(d) : "l"(a), "l"(b), "l"(c)); return d;
}
static __device__ __forceinline__ u64 mul2(u64 a, u64 b) {
    u64 d; asm("mul.rn.f32x2 %0,%1,%2;" : "=l"(d) : "l"(a), "l"(b)); return d;
}

// ---------------- mma.sync / ldmatrix helpers (sm_80+ PTX) ----------------
static __device__ __forceinline__ uint32_t smem_u32(const void* p) {
    uint32_t a;
    asm("{ .reg .u64 t; cvta.to.shared.u64 t, %1; cvt.u32.u64 %0, t; }" : "=r"(a) : "l"(p));
    return a;
}
static __device__ __forceinline__ void ldmat_x4(uint32_t* r, uint32_t addr) {
    asm volatile("ldmatrix.sync.aligned.m8n8.x4.shared.b16 {%0,%1,%2,%3}, [%4];"
        : "=r"(r[0]), "=r"(r[1]), "=r"(r[2]), "=r"(r[3]) : "r"(addr));
}
static __device__ __forceinline__ void ldmat_x2(uint32_t* r, uint32_t addr) {
    asm volatile("ldmatrix.sync.aligned.m8n8.x2.shared.b16 {%0,%1}, [%2];"
        : "=r"(r[0]), "=r"(r[1]) : "r"(addr));
}
static __device__ __forceinline__ void mma_f16(float* d, const uint32_t* a, const uint32_t* b) {
    asm volatile("mma.sync.aligned.m16n8k16.row.col.f32.f16.f16.f32 "
        "{%0,%1,%2,%3},{%4,%5,%6,%7},{%8,%9},{%0,%1,%2,%3};"
        : "+f"(d[0]), "+f"(d[1]), "+f"(d[2]), "+f"(d[3])
        : "r"(a[0]), "r"(a[1]), "r"(a[2]), "r"(a[3]), "r"(b[0]), "r"(b[1]));
}
static __device__ __forceinline__ uint32_t h2_u32(__half2 h) {
    union { __half2 h; uint32_t u; } c; c.h = h; return c.u;
}

// ---------------- fp16 1-term GEMM (NT): C = A[M,K] * B[N,K]^T -------------
// A, B rounded to fp16 during staging (error ~2^-12 each; measured rel_err
// 8.4e-5 end-to-end in R11). 1 MMA per (mt,nt) per k-step.
// Block tile 128x128, 512 threads / 16 warps (4x4 grid, 32x32 per warp),
// K chunk 64, double-buffered smem.
#define NTHR   512
#define KCH    64
#define ASTR   144                       // bytes per smem row (64 f16 + 8 pad)
#define TILE_B (128 * ASTR)              // 18432 B per tile
#define BUF_B  (2 * TILE_B)              // A, B = 36864 B
#define GEMM_SMEM (2 * BUF_B)            // 73728 B

// convert fp32 float4 -> fp16 rn, store at (row, c4..c4+3)
static __device__ __forceinline__ void cvt_store(float4 v, char* t, int row, int c4) {
    uint32_t off = (uint32_t)row * ASTR + (uint32_t)c4 * 2u;
    __half2 h01 = __floats2half2_rn(v.x, v.y);
    __half2 h23 = __floats2half2_rn(v.z, v.w);
    *(uint2*)(t + off) = make_uint2(h2_u32(h01), h2_u32(h23));
}

// EPI: 0 none; 1 +bias[n]+res[m,n]; 2 gelu(+bias[n]) exact
template <int EPI>
__global__ void __launch_bounds__(NTHR, 1)
gemm_mma(const float* __restrict__ A, const float* __restrict__ B,
         float* __restrict__ Cmat, const float* __restrict__ bias,
         const float* __restrict__ res, int M, int N, int K) {
    extern __shared__ char smem[];
    const uint32_t sb = smem_u32(smem);
    const int tid  = threadIdx.x;
    const int wid  = tid >> 5;
    const int lane = tid & 31;
    const int bm = blockIdx.y << 7;
    const int bn = blockIdx.x << 7;

    const int wm = (wid & 3) * 32;       // warp m-offset
    const int wn = (wid >> 2) * 32;      // warp n-offset

    const uint32_t aro = (uint32_t)(lane & 15) * ASTR + (uint32_t)(lane >> 4) * 16u;
    const uint32_t bro = (uint32_t)(lane & 7) * ASTR + (uint32_t)((lane >> 3) & 1) * 16u;

    float acc[2][4][4];
#pragma unroll
    for (int i = 0; i < 2; i++)
#pragma unroll
        for (int j = 0; j < 4; j++)
#pragma unroll
            for (int e = 0; e < 4; e++) acc[i][j][e] = 0.f;

    const int NC = K / KCH;

    // ---- stage chunk 0 into buffer 0 ----
    {
        char* bp = smem;
#pragma unroll
        for (int i = 0; i < 4; i++) {
            int f = i * NTHR + tid;
            int row = f >> 4, c4 = (f & 15) << 2;
            float4 v = *(const float4*)(A + (size_t)(bm + row) * K + c4);
            cvt_store(v, bp, row, c4);
        }
#pragma unroll
        for (int i = 0; i < 4; i++) {
            int f = i * NTHR + tid;
            int row = f >> 4, c4 = (f & 15) << 2;
            float4 v = *(const float4*)(B + (size_t)(bn + row) * K + c4);
            cvt_store(v, bp + TILE_B, row, c4);
        }
    }
    __syncthreads();

    for (int c = 0; c < NC; ++c) {
        // ---- prefetch chunk c+1 into other buffer ----
        if (c + 1 < NC) {
            char* bp = smem + ((c + 1) & 1) * BUF_B;
            const int kb = (c + 1) * KCH;
#pragma unroll
            for (int i = 0; i < 4; i++) {
                int f = i * NTHR + tid;
                int row = f >> 4, c4 = (f & 15) << 2;
                float4 v = *(const float4*)(A + (size_t)(bm + row) * K + kb + c4);
                cvt_store(v, bp, row, c4);
            }
#pragma unroll
            for (int i = 0; i < 4; i++) {
                int f = i * NTHR + tid;
                int row = f >> 4, c4 = (f & 15) << 2;
                float4 v = *(const float4*)(B + (size_t)(bn + row) * K + kb + c4);
                cvt_store(v, bp + TILE_B, row, c4);
            }
        }

        // ---- compute chunk c ----
        const uint32_t bufb = sb + (c & 1) * BUF_B;
        const uint32_t aT = bufb, bT = bufb + TILE_B;

#pragma unroll
        for (int ks = 0; ks < 4; ks++) {
            const uint32_t kso = (uint32_t)ks * 32u;
            uint32_t bh[4][2];
#pragma unroll
            for (int nt = 0; nt < 4; nt++) {
                const uint32_t ro = (uint32_t)(wn + nt * 8) * ASTR + kso + bro;
                ldmat_x2(bh[nt], bT + ro);
            }
            uint32_t ah[2][4];
#pragma unroll
            for (int mt = 0; mt < 2; mt++) {
                const uint32_t ro = (uint32_t)(wm + mt * 16) * ASTR + kso + aro;
                ldmat_x4(ah[mt], aT + ro);
            }
#pragma unroll
            for (int mt = 0; mt < 2; mt++)
#pragma unroll
                for (int nt = 0; nt < 4; nt++)
                    mma_f16(acc[mt][nt], ah[mt], bh[nt]);
        }
        __syncthreads();
    }

    // ---- epilogue from register fragments ----
    const int g   = lane >> 2;
    const int tig = lane & 3;
#pragma unroll
    for (int mt = 0; mt < 2; mt++) {
#pragma unroll
        for (int half = 0; half < 2; half++) {
            const int m = bm + wm + mt * 16 + g + 8 * half;
            float* crow = Cmat + (size_t)m * N;
            const float* rrow = (EPI == 1) ? (res + (size_t)m * N) : nullptr;
#pragma unroll
            for (int nt = 0; nt < 4; nt++) {
                const int cb = bn + wn + nt * 8 + 2 * tig;
                float v0 = acc[mt][nt][2 * half];
                float v1 = acc[mt][nt][2 * half + 1];
                if (EPI == 1) {
                    float2 rv = *(const float2*)(rrow + cb);
                    v0 += bias[cb] + rv.x;
                    v1 += bias[cb + 1] + rv.y;
                } else if (EPI == 2) {
                    float t0 = v0 + bias[cb], t1 = v1 + bias[cb + 1];
                    v0 = 0.5f * t0 * (1.0f + erff(t0 * 0.70710678118654752f));
                    v1 = 0.5f * t1 * (1.0f + erff(t1 * 0.70710678118654752f));
                }
                float2 ov = { v0, v1 };
                *(float2*)(crow + cb) = ov;
            }
        }
    }
}

// ---------------- LayerNorm: one warp per token ----------------
__global__ void ln_kernel(const float* __restrict__ x, const float* __restrict__ g,
                          const float* __restrict__ b, float* __restrict__ out) {
    const int warp = (blockIdx.x * 256 + threadIdx.x) >> 5;
    const int lane = threadIdx.x & 31;
    const float4* row = (const float4*)(x + (size_t)warp * CC);
    float4 v[4];
    float s = 0.f, q = 0.f;
#pragma unroll
    for (int i = 0; i < 4; i++) {
        v[i] = row[lane + 32 * i];
        s += v[i].x + v[i].y + v[i].z + v[i].w;
        q += v[i].x * v[i].x + v[i].y * v[i].y + v[i].z * v[i].z + v[i].w * v[i].w;
    }
#pragma unroll
    for (int o = 16; o; o >>= 1) {
        s += __shfl_xor_sync(0xFFFFFFFFu, s, o);
        q += __shfl_xor_sync(0xFFFFFFFFu, q, o);
    }
    const float mu  = s * (1.0f / CC);
    const float var = fmaxf(q * (1.0f / CC) - mu * mu, 0.0f);
    const float r   = rsqrtf(var + 1e-5f);

    float4* orow = (float4*)(out + (size_t)warp * CC);
    const float4* gg = (const float4*)g;
    const float4* bb = (const float4*)b;
#pragma unroll
    for (int i = 0; i < 4; i++) {
        float4 gv = gg[lane + 32 * i], bv = bb[lane + 32 * i], ov;
        ov.x = (v[i].x - mu) * r * gv.x + bv.x;
        ov.y = (v[i].y - mu) * r * gv.y + bv.y;
        ov.z = (v[i].z - mu) * r * gv.z + bv.z;
        ov.w = (v[i].w - mu) * r * gv.w + bv.w;
        orow[lane + 32 * i] = ov;
    }
}

// ---------------- Attention: one block per (seq, head), online softmax ------
__global__ void __launch_bounds__(256, 1)
attn_kernel(const float* __restrict__ qkv, float* __restrict__ o) {
    __shared__ float Ks[64 * 64];
    __shared__ float Vs[64 * 64];
    const int head = blockIdx.x;
    const int seqb = blockIdx.y * SEQ;
    const int tid  = threadIdx.x;
    const int tq   = seqb + tid;

    u64 q2[32], o2[32];
    {
        const float4* qp = (const float4*)(qkv + (size_t)tq * C3 + head * HDIM);
#pragma unroll
        for (int t = 0; t < 16; t++) {
            float4 v = qp[t];
            q2[2 * t]     = pack2(v.x * 0.125f, v.y * 0.125f);
            q2[2 * t + 1] = pack2(v.z * 0.125f, v.w * 0.125f);
            o2[2 * t] = 0ull; o2[2 * t + 1] = 0ull;
        }
    }
    float mx = -1e30f, sm = 0.f;

    for (int ck = 0; ck < 4; ++ck) {
        __syncthreads();
#pragma unroll
        for (int it = 0; it < 4; ++it) {
            const int idx = it * 256 + tid;
            const int r = idx >> 4, c4 = idx & 15;
            const float* base = qkv + (size_t)(seqb + ck * 64 + r) * C3 + head * HDIM + c4 * 4;
            ((float4*)Ks)[idx] = *(const float4*)(base + 512);
            ((float4*)Vs)[idx] = *(const float4*)(base + 1024);
        }
        __syncthreads();

        for (int m = 0; m < 64; m++) {
            const u64* K2 = (const u64*)(Ks + m * 64);
            u64 s4[4] = { 0ull, 0ull, 0ull, 0ull };
#pragma unroll
            for (int j = 0; j < 32; j += 4) {
                s4[0] = fma2(q2[j + 0], K2[j + 0], s4[0]);
                s4[1] = fma2(q2[j + 1], K2[j + 1], s4[1]);
                s4[2] = fma2(q2[j + 2], K2[j + 2], s4[2]);
                s4[3] = fma2(q2[j + 3], K2[j + 3], s4[3]);
            }
            float2 p0 = unpack2(s4[0]), p1 = unpack2(s4[1]);
            float2 p2 = unpack2(s4[2]), p3 = unpack2(s4[3]);
            const float s = ((p0.x + p0.y) + (p1.x + p1.y)) + ((p2.x + p2.y) + (p3.x + p3.y));

            const float mn   = fmaxf(mx, s);
            const float corr = __expf(mx - mn);
            const float p    = __expf(s - mn);
            sm = sm * corr + p;
            mx = mn;

            const u64 cd = pack2(corr, corr);
            const u64 pd = pack2(p, p);
            const u64* V2 = (const u64*)(Vs + m * 64);
#pragma unroll
            for (int j = 0; j < 32; j++)
                o2[j] = fma2(o2[j], cd, mul2(pd, V2[j]));
        }
    }

    const float inv = 1.0f / sm;
    float4* op = (float4*)(o + (size_t)tq * CC + head * HDIM);
#pragma unroll
    for (int t = 0; t < 16; t++) {
        float2 a = unpack2(o2[2 * t]);
        float2 b = unpack2(o2[2 * t + 1]);
        float4 v = { a.x * inv, a.y * inv, b.x * inv, b.y * inv };
        op[t] = v;
    }
}

// ---------------- launcher ----------------
extern "C" void kernel_launch(void* const* d_in, const int* in_sizes, int n_in,
                              void* d_out, int out_size) {
    const float* x     = (const float*)d_in[0];
    const float* ln1g  = (const float*)d_in[1];
    const float* ln1b  = (const float*)d_in[2];
    const float* wqkv  = (const float*)d_in[3];
    const float* wproj = (const float*)d_in[4];
    const float* bproj = (const float*)d_in[5];
    const float* ln2g  = (const float*)d_in[6];
    const float* ln2b  = (const float*)d_in[7];
    const float* w1    = (const float*)d_in[8];
    const float* b1    = (const float*)d_in[9];
    const float* w2    = (const float*)d_in[10];
    const float* b2    = (const float*)d_in[11];
    float* out = (float*)d_out;

    float *h1, *qkv, *o, *x1, *h2, *ff;
    cudaGetSymbolAddress((void**)&h1,  g_h1);
    cudaGetSymbolAddress((void**)&qkv, g_qkv);
    cudaGetSymbolAddress((void**)&o,   g_o);
    cudaGetSymbolAddress((void**)&x1,  g_x1);
    cudaGetSymbolAddress((void**)&h2,  g_h2);
    cudaGetSymbolAddress((void**)&ff,  g_ff);

    cudaFuncSetAttribute(gemm_mma<0>, cudaFuncAttributeMaxDynamicSharedMemorySize, GEMM_SMEM);
    cudaFuncSetAttribute(gemm_mma<1>, cudaFuncAttributeMaxDynamicSharedMemorySize, GEMM_SMEM);
    cudaFuncSetAttribute(gemm_mma<2>, cudaFuncAttributeMaxDynamicSharedMemorySize, GEMM_SMEM);

    // 1) LN1
    ln_kernel<<<TT / 8, 256>>>(x, ln1g, ln1b, h1);
    // 2) QKV = h1 @ w_qkv^T
    gemm_mma<0><<<dim3(C3 / 128, TT / 128), NTHR, GEMM_SMEM>>>(h1, wqkv, qkv, nullptr, nullptr, TT, C3, CC);
    // 3) attention
    attn_kernel<<<dim3(NHEAD, NSEQ), 256>>>(qkv, o);
    // 4) x1 = x + o @ w_proj^T + b_proj
    gemm_mma<1><<<dim3(CC / 128, TT / 128), NTHR, GEMM_SMEM>>>(o, wproj, x1, bproj, x, TT, CC, CC);
    // 5) LN2
    ln_kernel<<<TT / 8, 256>>>(x1, ln2g, ln2b, h2);
    // 6) ff = gelu(h2 @ w1^T + b1)
    gemm_mma<2><<<dim3(HID / 128, TT / 128), NTHR, GEMM_SMEM>>>(h2, w1, ff, b1, nullptr, TT, HID, CC);
    // 7) out = x1 + ff @ w2^T + b2
    gemm_mma<1><<<dim3(CC / 128, TT / 128), NTHR, GEMM_SMEM>>>(ff, w2, out, b2, x1, TT, CC, HID);
}

// round 14
// speedup vs baseline: 1.4331x; 1.0242x over previous
#include <cuda_runtime.h>
#include <cuda_fp16.h>
#include <math.h>
#include <stdint.h>

// ---------------- problem constants ----------------
#define TT    16384
#define CC    512
#define C3    1536
#define HID   2048
#define NHEAD 8
#define HDIM  64
#define SEQ   256
#define NSEQ  64

typedef unsigned long long u64;

// ---------------- scratch ----------------
__device__ float  g_h1 [(size_t)TT * CC];
__device__ float  g_qkv[(size_t)TT * C3];
__device__ float  g_o  [(size_t)TT * CC];
__device__ float  g_x1 [(size_t)TT * CC];
__device__ float  g_h2 [(size_t)TT * CC];
__device__ float  g_ff [(size_t)TT * HID];
__device__ __half g_wqkvh [(size_t)C3 * CC];   // fp16 weights (converted once)
__device__ __half g_wprojh[(size_t)CC * CC];
__device__ __half g_w1h   [(size_t)HID * CC];
__device__ __half g_w2h   [(size_t)CC * HID];

// ---------------- f32x2 helpers (attention) ----------------
static __device__ __forceinline__ u64 pack2(float lo, float hi) {
    u64 r; asm("mov.b64 %0,{%1,%2};" : "=l"(r) : "f"(lo), "f"(hi)); return r;
}
static __device__ __forceinline__ float2 unpack2(u64 v) {
    float2 r; asm("mov.b64 {%0,%1},%2;" : "=f"(r.x), "=f"(r.y) : "l"(v)); return r;
}
static __device__ __forceinline__ u64 fma2(u64 a, u64 b, u64 c) {
    u64 d; asm("fma.rn.f32x2 %0,%1,%2,%3;" : "=l"(d) : "l"(a), "l"(b), "l"(c)); return d;
}
static __device__ __forceinline__ u64 mul2(u64 a, u64 b) {
    u64 d; asm("mul.rn.f32x2 %0,%1,%2;" : "=l"(d) : "l"(a), "l"(b)); return d;
}

// ---------------- mma.sync / ldmatrix helpers (sm_80+ PTX) ----------------
static __device__ __forceinline__ uint32_t smem_u32(const void* p) {
    uint32_t a;
    asm("{ .reg .u64 t; cvta.to.shared.u64 t, %1; cvt.u32.u64 %0, t; }" : "=r"(a) : "l"(p));
    return a;
}
static __device__ __forceinline__ void ldmat_x4(uint32_t* r, uint32_t addr) {
    asm volatile("ldmatrix.sync.aligned.m8n8.x4.shared.b16 {%0,%1,%2,%3}, [%4];"
        : "=r"(r[0]), "=r"(r[1]), "=r"(r[2]), "=r"(r[3]) : "r"(addr));
}
static __device__ __forceinline__ void ldmat_x2(uint32_t* r, uint32_t addr) {
    asm volatile("ldmatrix.sync.aligned.m8n8.x2.shared.b16 {%0,%1}, [%2];"
        : "=r"(r[0]), "=r"(r[1]) : "r"(addr));
}
static __device__ __forceinline__ void mma_f16(float* d, const uint32_t* a, const uint32_t* b) {
    asm volatile("mma.sync.aligned.m16n8k16.row.col.f32.f16.f16.f32 "
        "{%0,%1,%2,%3},{%4,%5,%6,%7},{%8,%9},{%0,%1,%2,%3};"
        : "+f"(d[0]), "+f"(d[1]), "+f"(d[2]), "+f"(d[3])
        : "r"(a[0]), "r"(a[1]), "r"(a[2]), "r"(a[3]), "r"(b[0]), "r"(b[1]));
}
static __device__ __forceinline__ uint32_t h2_u32(__half2 h) {
    union { __half2 h; uint32_t u; } c; c.h = h; return c.u;
}

// ---------------- weight fp32 -> fp16 prep (once per launch) ----------------
__global__ void cvt_h_kernel(const float* __restrict__ in, __half* __restrict__ out) {
    const int i = (blockIdx.x * 256 + threadIdx.x) * 4;
    float4 v = *(const float4*)(in + i);
    __half2 a = __floats2half2_rn(v.x, v.y);
    __half2 b = __floats2half2_rn(v.z, v.w);
    *(uint2*)(out + i) = make_uint2(h2_u32(a), h2_u32(b));
}

// ---------------- fp16 1-term GEMM (NT): C = A[M,K] * B[N,K]^T -------------
// A fp32 (converted during staging); B already fp16 in global (raw copy).
// Block tile 128x128, 512 threads / 16 warps (4x4 grid, 32x32 per warp),
// K chunk 64, double-buffered smem.
#define NTHR   512
#define KCH    64
#define ASTR   144                       // bytes per smem row (64 f16 + 8 pad)
#define TILE_B (128 * ASTR)              // 18432 B per tile
#define BUF_B  (2 * TILE_B)              // A, B = 36864 B
#define GEMM_SMEM (2 * BUF_B)            // 73728 B

// convert fp32 float4 -> fp16 rn, store at (row, c4..c4+3)
static __device__ __forceinline__ void cvt_store(float4 v, char* t, int row, int c4) {
    uint32_t off = (uint32_t)row * ASTR + (uint32_t)c4 * 2u;
    __half2 h01 = __floats2half2_rn(v.x, v.y);
    __half2 h23 = __floats2half2_rn(v.z, v.w);
    *(uint2*)(t + off) = make_uint2(h2_u32(h01), h2_u32(h23));
}

// EPI: 0 none; 1 +bias[n]+res[m,n]; 2 gelu(+bias[n]) exact
template <int EPI>
__global__ void __launch_bounds__(NTHR, 1)
gemm_mma(const float* __restrict__ A, const __half* __restrict__ B,
         float* __restrict__ Cmat, const float* __restrict__ bias,
         const float* __restrict__ res, int M, int N, int K) {
    extern __shared__ char smem[];
    const uint32_t sb = smem_u32(smem);
    const int tid  = threadIdx.x;
    const int wid  = tid >> 5;
    const int lane = tid & 31;
    const int bm = blockIdx.y << 7;
    const int bn = blockIdx.x << 7;

    const int wm = (wid & 3) * 32;       // warp m-offset
    const int wn = (wid >> 2) * 32;      // warp n-offset

    const uint32_t aro = (uint32_t)(lane & 15) * ASTR + (uint32_t)(lane >> 4) * 16u;
    const uint32_t bro = (uint32_t)(lane & 7) * ASTR + (uint32_t)((lane >> 3) & 1) * 16u;

    float acc[2][4][4];
#pragma unroll
    for (int i = 0; i < 2; i++)
#pragma unroll
        for (int j = 0; j < 4; j++)
#pragma unroll
            for (int e = 0; e < 4; e++) acc[i][j][e] = 0.f;

    const int NC = K / KCH;

    // ---- stage chunk 0 into buffer 0 ----
    {
        char* bp = smem;
#pragma unroll
        for (int i = 0; i < 4; i++) {
            int f = i * NTHR + tid;
            int row = f >> 4, c4 = (f & 15) << 2;
            float4 v = *(const float4*)(A + (size_t)(bm + row) * K + c4);
            cvt_store(v, bp, row, c4);
        }
#pragma unroll
        for (int i = 0; i < 2; i++) {     // B: raw fp16 copy, 2 uint4/thread
            int f = i * NTHR + tid;
            int row = f >> 3, c8 = (f & 7) << 3;
            uint4 v = *(const uint4*)(B + (size_t)(bn + row) * K + c8);
            *(uint4*)(bp + TILE_B + (uint32_t)row * ASTR + (uint32_t)c8 * 2u) = v;
        }
    }
    __syncthreads();

    for (int c = 0; c < NC; ++c) {
        // ---- prefetch chunk c+1 into other buffer ----
        if (c + 1 < NC) {
            char* bp = smem + ((c + 1) & 1) * BUF_B;
            const int kb = (c + 1) * KCH;
#pragma unroll
            for (int i = 0; i < 4; i++) {
                int f = i * NTHR + tid;
                int row = f >> 4, c4 = (f & 15) << 2;
                float4 v = *(const float4*)(A + (size_t)(bm + row) * K + kb + c4);
                cvt_store(v, bp, row, c4);
            }
#pragma unroll
            for (int i = 0; i < 2; i++) {
                int f = i * NTHR + tid;
                int row = f >> 3, c8 = (f & 7) << 3;
                uint4 v = *(const uint4*)(B + (size_t)(bn + row) * K + kb + c8);
                *(uint4*)(bp + TILE_B + (uint32_t)row * ASTR + (uint32_t)c8 * 2u) = v;
            }
        }

        // ---- compute chunk c ----
        const uint32_t bufb = sb + (c & 1) * BUF_B;
        const uint32_t aT = bufb, bT = bufb + TILE_B;

#pragma unroll
        for (int ks = 0; ks < 4; ks++) {
            const uint32_t kso = (uint32_t)ks * 32u;
            uint32_t bh[4][2];
#pragma unroll
            for (int nt = 0; nt < 4; nt++) {
                const uint32_t ro = (uint32_t)(wn + nt * 8) * ASTR + kso + bro;
                ldmat_x2(bh[nt], bT + ro);
            }
            uint32_t ah[2][4];
#pragma unroll
            for (int mt = 0; mt < 2; mt++) {
                const uint32_t ro = (uint32_t)(wm + mt * 16) * ASTR + kso + aro;
                ldmat_x4(ah[mt], aT + ro);
            }
#pragma unroll
            for (int mt = 0; mt < 2; mt++)
#pragma unroll
                for (int nt = 0; nt < 4; nt++)
                    mma_f16(acc[mt][nt], ah[mt], bh[nt]);
        }
        __syncthreads();
    }

    // ---- epilogue from register fragments ----
    const int g   = lane >> 2;
    const int tig = lane & 3;
#pragma unroll
    for (int mt = 0; mt < 2; mt++) {
#pragma unroll
        for (int half = 0; half < 2; half++) {
            const int m = bm + wm + mt * 16 + g + 8 * half;
            float* crow = Cmat + (size_t)m * N;
            const float* rrow = (EPI == 1) ? (res + (size_t)m * N) : nullptr;
#pragma unroll
            for (int nt = 0; nt < 4; nt++) {
                const int cb = bn + wn + nt * 8 + 2 * tig;
                float v0 = acc[mt][nt][2 * half];
                float v1 = acc[mt][nt][2 * half + 1];
                if (EPI == 1) {
                    float2 rv = *(const float2*)(rrow + cb);
                    v0 += bias[cb] + rv.x;
                    v1 += bias[cb + 1] + rv.y;
                } else if (EPI == 2) {
                    float t0 = v0 + bias[cb], t1 = v1 + bias[cb + 1];
                    v0 = 0.5f * t0 * (1.0f + erff(t0 * 0.70710678118654752f));
                    v1 = 0.5f * t1 * (1.0f + erff(t1 * 0.70710678118654752f));
                }
                float2 ov = { v0, v1 };
                *(float2*)(crow + cb) = ov;
            }
        }
    }
}

// ---------------- LayerNorm: one warp per token ----------------
__global__ void ln_kernel(const float* __restrict__ x, const float* __restrict__ g,
                          const float* __restrict__ b, float* __restrict__ out) {
    const int warp = (blockIdx.x * 256 + threadIdx.x) >> 5;
    const int lane = threadIdx.x & 31;
    const float4* row = (const float4*)(x + (size_t)warp * CC);
    float4 v[4];
    float s = 0.f, q = 0.f;
#pragma unroll
    for (int i = 0; i < 4; i++) {
        v[i] = row[lane + 32 * i];
        s += v[i].x + v[i].y + v[i].z + v[i].w;
        q += v[i].x * v[i].x + v[i].y * v[i].y + v[i].z * v[i].z + v[i].w * v[i].w;
    }
#pragma unroll
    for (int o = 16; o; o >>= 1) {
        s += __shfl_xor_sync(0xFFFFFFFFu, s, o);
        q += __shfl_xor_sync(0xFFFFFFFFu, q, o);
    }
    const float mu  = s * (1.0f / CC);
    const float var = fmaxf(q * (1.0f / CC) - mu * mu, 0.0f);
    const float r   = rsqrtf(var + 1e-5f);

    float4* orow = (float4*)(out + (size_t)warp * CC);
    const float4* gg = (const float4*)g;
    const float4* bb = (const float4*)b;
#pragma unroll
    for (int i = 0; i < 4; i++) {
        float4 gv = gg[lane + 32 * i], bv = bb[lane + 32 * i], ov;
        ov.x = (v[i].x - mu) * r * gv.x + bv.x;
        ov.y = (v[i].y - mu) * r * gv.y + bv.y;
        ov.z = (v[i].z - mu) * r * gv.z + bv.z;
        ov.w = (v[i].w - mu) * r * gv.w + bv.w;
        orow[lane + 32 * i] = ov;
    }
}

// ---------------- Attention: one block per (seq, head), online softmax ------
__global__ void __launch_bounds__(256, 1)
attn_kernel(const float* __restrict__ qkv, float* __restrict__ o) {
    __shared__ float Ks[64 * 64];
    __shared__ float Vs[64 * 64];
    const int head = blockIdx.x;
    const int seqb = blockIdx.y * SEQ;
    const int tid  = threadIdx.x;
    const int tq   = seqb + tid;

    u64 q2[32], o2[32];
    {
        const float4* qp = (const float4*)(qkv + (size_t)tq * C3 + head * HDIM);
#pragma unroll
        for (int t = 0; t < 16; t++) {
            float4 v = qp[t];
            q2[2 * t]     = pack2(v.x * 0.125f, v.y * 0.125f);
            q2[2 * t + 1] = pack2(v.z * 0.125f, v.w * 0.125f);
            o2[2 * t] = 0ull; o2[2 * t + 1] = 0ull;
        }
    }
    float mx = -1e30f, sm = 0.f;

    for (int ck = 0; ck < 4; ++ck) {
        __syncthreads();
#pragma unroll
        for (int it = 0; it < 4; ++it) {
            const int idx = it * 256 + tid;
            const int r = idx >> 4, c4 = idx & 15;
            const float* base = qkv + (size_t)(seqb + ck * 64 + r) * C3 + head * HDIM + c4 * 4;
            ((float4*)Ks)[idx] = *(const float4*)(base + 512);
            ((float4*)Vs)[idx] = *(const float4*)(base + 1024);
        }
        __syncthreads();

        for (int m = 0; m < 64; m++) {
            const u64* K2 = (const u64*)(Ks + m * 64);
            u64 s4[4] = { 0ull, 0ull, 0ull, 0ull };
#pragma unroll
            for (int j = 0; j < 32; j += 4) {
                s4[0] = fma2(q2[j + 0], K2[j + 0], s4[0]);
                s4[1] = fma2(q2[j + 1], K2[j + 1], s4[1]);
                s4[2] = fma2(q2[j + 2], K2[j + 2], s4[2]);
                s4[3] = fma2(q2[j + 3], K2[j + 3], s4[3]);
            }
            float2 p0 = unpack2(s4[0]), p1 = unpack2(s4[1]);
            float2 p2 = unpack2(s4[2]), p3 = unpack2(s4[3]);
            const float s = ((p0.x + p0.y) + (p1.x + p1.y)) + ((p2.x + p2.y) + (p3.x + p3.y));

            const float mn   = fmaxf(mx, s);
            const float corr = __expf(mx - mn);
            const float p    = __expf(s - mn);
            sm = sm * corr + p;
            mx = mn;

            const u64 cd = pack2(corr, corr);
            const u64 pd = pack2(p, p);
            const u64* V2 = (const u64*)(Vs + m * 64);
#pragma unroll
            for (int j = 0; j < 32; j++)
                o2[j] = fma2(o2[j], cd, mul2(pd, V2[j]));
        }
    }

    const float inv = 1.0f / sm;
    float4* op = (float4*)(o + (size_t)tq * CC + head * HDIM);
#pragma unroll
    for (int t = 0; t < 16; t++) {
        float2 a = unpack2(o2[2 * t]);
        float2 b = unpack2(o2[2 * t + 1]);
        float4 v = { a.x * inv, a.y * inv, b.x * inv, b.y * inv };
        op[t] = v;
    }
}

// ---------------- launcher ----------------
extern "C" void kernel_launch(void* const* d_in, const int* in_sizes, int n_in,
                              void* d_out, int out_size) {
    const float* x     = (const float*)d_in[0];
    const float* ln1g  = (const float*)d_in[1];
    const float* ln1b  = (const float*)d_in[2];
    const float* wqkv  = (const float*)d_in[3];
    const float* wproj = (const float*)d_in[4];
    const float* bproj = (const float*)d_in[5];
    const float* ln2g  = (const float*)d_in[6];
    const float* ln2b  = (const float*)d_in[7];
    const float* w1    = (const float*)d_in[8];
    const float* b1    = (const float*)d_in[9];
    const float* w2    = (const float*)d_in[10];
    const float* b2    = (const float*)d_in[11];
    float* out = (float*)d_out;

    float *h1, *qkv, *o, *x1, *h2, *ff;
    __half *wqkvh, *wprojh, *w1h, *w2h;
    cudaGetSymbolAddress((void**)&h1,    g_h1);
    cudaGetSymbolAddress((void**)&qkv,   g_qkv);
    cudaGetSymbolAddress((void**)&o,     g_o);
    cudaGetSymbolAddress((void**)&x1,    g_x1);
    cudaGetSymbolAddress((void**)&h2,    g_h2);
    cudaGetSymbolAddress((void**)&ff,    g_ff);
    cudaGetSymbolAddress((void**)&wqkvh, g_wqkvh);
    cudaGetSymbolAddress((void**)&wprojh,g_wprojh);
    cudaGetSymbolAddress((void**)&w1h,   g_w1h);
    cudaGetSymbolAddress((void**)&w2h,   g_w2h);

    cudaFuncSetAttribute(gemm_mma<0>, cudaFuncAttributeMaxDynamicSharedMemorySize, GEMM_SMEM);
    cudaFuncSetAttribute(gemm_mma<1>, cudaFuncAttributeMaxDynamicSharedMemorySize, GEMM_SMEM);
    cudaFuncSetAttribute(gemm_mma<2>, cudaFuncAttributeMaxDynamicSharedMemorySize, GEMM_SMEM);

    // 0) weight fp32 -> fp16 once (numerics identical to staging-side rn cvt)
    cvt_h_kernel<<<(C3 * CC) / 1024, 256>>>(wqkv, wqkvh);
    cvt_h_kernel<<<(CC * CC) / 1024, 256>>>(wproj, wprojh);
    cvt_h_kernel<<<(HID * CC) / 1024, 256>>>(w1, w1h);
    cvt_h_kernel<<<(CC * HID) / 1024, 256>>>(w2, w2h);

    // 1) LN1
    ln_kernel<<<TT / 8, 256>>>(x, ln1g, ln1b, h1);
    // 2) QKV = h1 @ w_qkv^T
    gemm_mma<0><<<dim3(C3 / 128, TT / 128), NTHR, GEMM_SMEM>>>(h1, wqkvh, qkv, nullptr, nullptr, TT, C3, CC);
    // 3) attention
    attn_kernel<<<dim3(NHEAD, NSEQ), 256>>>(qkv, o);
    // 4) x1 = x + o @ w_proj^T + b_proj
    gemm_mma<1><<<dim3(CC / 128, TT / 128), NTHR, GEMM_SMEM>>>(o, wprojh, x1, bproj, x, TT, CC, CC);
    // 5) LN2
    ln_kernel<<<TT / 8, 256>>>(x1, ln2g, ln2b, h2);
    // 6) ff = gelu(h2 @ w1^T + b1)
    gemm_mma<2><<<dim3(HID / 128, TT / 128), NTHR, GEMM_SMEM>>>(h2, w1h, ff, b1, nullptr, TT, HID, CC);
    // 7) out = x1 + ff @ w2^T + b2
    gemm_mma<1><<<dim3(CC / 128, TT / 128), NTHR, GEMM_SMEM>>>(ff, w2h, out, b2, x1, TT, CC, HID);
}

// round 15
// speedup vs baseline: 1.6950x; 1.1828x over previous
#include <cuda_runtime.h>
#include <cuda_fp16.h>
#include <math.h>
#include <stdint.h>

// ---------------- problem constants ----------------
#define TT    16384
#define CC    512
#define C3    1536
#define HID   2048
#define NHEAD 8
#define HDIM  64
#define SEQ   256
#define NSEQ  64

typedef unsigned long long u64;

// ---------------- scratch ----------------
__device__ __half g_h1h [(size_t)TT * CC];    // ln1 out (fp16, GEMM-A only)
__device__ float  g_qkv [(size_t)TT * C3];    // qkv (fp32: attention precision)
__device__ __half g_oh  [(size_t)TT * CC];    // attention out (fp16, GEMM-A only)
__device__ float  g_x1  [(size_t)TT * CC];    // x + proj (fp32: residual)
__device__ __half g_h2h [(size_t)TT * CC];    // ln2 out (fp16, GEMM-A only)
__device__ __half g_ffh [(size_t)TT * HID];   // gelu out (fp16, GEMM-A only)
__device__ __half g_wqkvh [(size_t)C3 * CC];  // fp16 weights (converted once)
__device__ __half g_wprojh[(size_t)CC * CC];
__device__ __half g_w1h   [(size_t)HID * CC];
__device__ __half g_w2h   [(size_t)CC * HID];

// ---------------- f32x2 helpers (attention) ----------------
static __device__ __forceinline__ u64 pack2(float lo, float hi) {
    u64 r; asm("mov.b64 %0,{%1,%2};" : "=l"(r) : "f"(lo), "f"(hi)); return r;
}
static __device__ __forceinline__ float2 unpack2(u64 v) {
    float2 r; asm("mov.b64 {%0,%1},%2;" : "=f"(r.x), "=f"(r.y) : "l"(v)); return r;
}
static __device__ __forceinline__ u64 fma2(u64 a, u64 b, u64 c) {
    u64 d; asm("fma.rn.f32x2 %0,%1,%2,%3;" : "=l"(d) : "l"(a), "l"(b), "l"(c)); return d;
}
static __device__ __forceinline__ u64 mul2(u64 a, u64 b) {
    u64 d; asm("mul.rn.f32x2 %0,%1,%2;" : "=l"(d) : "l"(a), "l"(b)); return d;
}

// ---------------- mma.sync / ldmatrix / cp.async helpers (sm_80+ PTX) -------
static __device__ __forceinline__ uint32_t smem_u32(const void* p) {
    uint32_t a;
    asm("{ .reg .u64 t; cvta.to.shared.u64 t, %1; cvt.u32.u64 %0, t; }" : "=r"(a) : "l"(p));
    return a;
}
static __device__ __forceinline__ void ldmat_x4(uint32_t* r, uint32_t addr) {
    asm volatile("ldmatrix.sync.aligned.m8n8.x4.shared.b16 {%0,%1,%2,%3}, [%4];"
        : "=r"(r[0]), "=r"(r[1]), "=r"(r[2]), "=r"(r[3]) : "r"(addr));
}
static __device__ __forceinline__ void ldmat_x2(uint32_t* r, uint32_t addr) {
    asm volatile("ldmatrix.sync.aligned.m8n8.x2.shared.b16 {%0,%1}, [%2];"
        : "=r"(r[0]), "=r"(r[1]) : "r"(addr));
}
static __device__ __forceinline__ void mma_f16(float* d, const uint32_t* a, const uint32_t* b) {
    asm volatile("mma.sync.aligned.m16n8k16.row.col.f32.f16.f16.f32 "
        "{%0,%1,%2,%3},{%4,%5,%6,%7},{%8,%9},{%0,%1,%2,%3};"
        : "+f"(d[0]), "+f"(d[1]), "+f"(d[2]), "+f"(d[3])
        : "r"(a[0]), "r"(a[1]), "r"(a[2]), "r"(a[3]), "r"(b[0]), "r"(b[1]));
}
static __device__ __forceinline__ uint32_t h2_u32(__half2 h) {
    union { __half2 h; uint32_t u; } c; c.h = h; return c.u;
}
static __device__ __forceinline__ void cp_async16(uint32_t dst, const void* src) {
    asm volatile("cp.async.cg.shared.global [%0], [%1], 16;" :: "r"(dst), "l"(src));
}
#define CP_COMMIT() asm volatile("cp.async.commit_group;" ::: "memory")
#define CP_WAIT0()  asm volatile("cp.async.wait_group 0;" ::: "memory")

// ---------------- weight fp32 -> fp16 prep (once per launch) ----------------
__global__ void cvt_h_kernel(const float* __restrict__ in, __half* __restrict__ out) {
    const int i = (blockIdx.x * 256 + threadIdx.x) * 4;
    float4 v = *(const float4*)(in + i);
    __half2 a = __floats2half2_rn(v.x, v.y);
    __half2 b = __floats2half2_rn(v.z, v.w);
    *(uint2*)(out + i) = make_uint2(h2_u32(a), h2_u32(b));
}

// ---------------- fp16 GEMM (NT): C = A[M,K] * B[N,K]^T, cp.async staged ----
// A and B both fp16 in global; staging = 4x cp.async 16B per thread per chunk.
// Block tile 128x128, 512 threads / 16 warps (4x4 grid, 32x32 per warp),
// K chunk 64, double-buffered smem.
#define NTHR   512
#define KCH    64
#define ASTR   144                       // bytes per smem row (64 f16 + 8 pad; 16B-aligned)
#define TILE_B (128 * ASTR)              // 18432 B per tile
#define BUF_B  (2 * TILE_B)              // A, B = 36864 B
#define GEMM_SMEM (2 * BUF_B)            // 73728 B

// EPI: 0 = fp32 out; 1 = fp32 out +bias[n]+res[m,n]; 2 = fp16 out gelu(+bias[n])
template <int EPI>
__global__ void __launch_bounds__(NTHR, 1)
gemm_mma(const __half* __restrict__ A, const __half* __restrict__ B,
         void* __restrict__ Cmat, const float* __restrict__ bias,
         const float* __restrict__ res, int M, int N, int K) {
    extern __shared__ char smem[];
    const uint32_t sb = smem_u32(smem);
    const int tid  = threadIdx.x;
    const int wid  = tid >> 5;
    const int lane = tid & 31;
    const int bm = blockIdx.y << 7;
    const int bn = blockIdx.x << 7;

    const int wm = (wid & 3) * 32;       // warp m-offset
    const int wn = (wid >> 2) * 32;      // warp n-offset

    const uint32_t aro = (uint32_t)(lane & 15) * ASTR + (uint32_t)(lane >> 4) * 16u;
    const uint32_t bro = (uint32_t)(lane & 7) * ASTR + (uint32_t)((lane >> 3) & 1) * 16u;

    // per-thread staging coordinates (16B granules): 2 per tile
    const int r0 = tid >> 3,               c80 = (tid & 7) << 3;
    const int r1 = (NTHR + tid) >> 3,      c81 = ((NTHR + tid) & 7) << 3;

    float acc[2][4][4];
#pragma unroll
    for (int i = 0; i < 2; i++)
#pragma unroll
        for (int j = 0; j < 4; j++)
#pragma unroll
            for (int e = 0; e < 4; e++) acc[i][j][e] = 0.f;

    const int NC = K / KCH;

    // ---- prologue: issue chunk 0 into buffer 0 ----
    {
        const uint32_t bp = sb;
        cp_async16(bp + (uint32_t)r0 * ASTR + (uint32_t)c80 * 2u, A + (size_t)(bm + r0) * K + c80);
        cp_async16(bp + (uint32_t)r1 * ASTR + (uint32_t)c81 * 2u, A + (size_t)(bm + r1) * K + c81);
        cp_async16(bp + TILE_B + (uint32_t)r0 * ASTR + (uint32_t)c80 * 2u, B + (size_t)(bn + r0) * K + c80);
        cp_async16(bp + TILE_B + (uint32_t)r1 * ASTR + (uint32_t)c81 * 2u, B + (size_t)(bn + r1) * K + c81);
        CP_COMMIT();
    }

    for (int c = 0; c < NC; ++c) {
        CP_WAIT0();
        __syncthreads();   // chunk c resident; all reads of buf (c-1)&1 done

        // ---- issue prefetch of chunk c+1 into other buffer ----
        if (c + 1 < NC) {
            const uint32_t bp = sb + ((c + 1) & 1) * BUF_B;
            const int kb = (c + 1) * KCH;
            cp_async16(bp + (uint32_t)r0 * ASTR + (uint32_t)c80 * 2u, A + (size_t)(bm + r0) * K + kb + c80);
            cp_async16(bp + (uint32_t)r1 * ASTR + (uint32_t)c81 * 2u, A + (size_t)(bm + r1) * K + kb + c81);
            cp_async16(bp + TILE_B + (uint32_t)r0 * ASTR + (uint32_t)c80 * 2u, B + (size_t)(bn + r0) * K + kb + c80);
            cp_async16(bp + TILE_B + (uint32_t)r1 * ASTR + (uint32_t)c81 * 2u, B + (size_t)(bn + r1) * K + kb + c81);
            CP_COMMIT();
        }

        // ---- compute chunk c ----
        const uint32_t bufb = sb + (c & 1) * BUF_B;
        const uint32_t aT = bufb, bT = bufb + TILE_B;

#pragma unroll
        for (int ks = 0; ks < 4; ks++) {
            const uint32_t kso = (uint32_t)ks * 32u;
            uint32_t bh[4][2];
#pragma unroll
            for (int nt = 0; nt < 4; nt++) {
                const uint32_t ro = (uint32_t)(wn + nt * 8) * ASTR + kso + bro;
                ldmat_x2(bh[nt], bT + ro);
            }
            uint32_t ah[2][4];
#pragma unroll
            for (int mt = 0; mt < 2; mt++) {
                const uint32_t ro = (uint32_t)(wm + mt * 16) * ASTR + kso + aro;
                ldmat_x4(ah[mt], aT + ro);
            }
#pragma unroll
            for (int mt = 0; mt < 2; mt++)
#pragma unroll
                for (int nt = 0; nt < 4; nt++)
                    mma_f16(acc[mt][nt], ah[mt], bh[nt]);
        }
    }

    // ---- epilogue from register fragments ----
    const int g   = lane >> 2;
    const int tig = lane & 3;
#pragma unroll
    for (int mt = 0; mt < 2; mt++) {
#pragma unroll
        for (int half = 0; half < 2; half++) {
            const int m = bm + wm + mt * 16 + g + 8 * half;
            const float* rrow = (EPI == 1) ? (res + (size_t)m * N) : nullptr;
#pragma unroll
            for (int nt = 0; nt < 4; nt++) {
                const int cb = bn + wn + nt * 8 + 2 * tig;
                float v0 = acc[mt][nt][2 * half];
                float v1 = acc[mt][nt][2 * half + 1];
                if (EPI == 1) {
                    float2 rv = *(const float2*)(rrow + cb);
                    v0 += bias[cb] + rv.x;
                    v1 += bias[cb + 1] + rv.y;
                    float2 ov = { v0, v1 };
                    *(float2*)((float*)Cmat + (size_t)m * N + cb) = ov;
                } else if (EPI == 2) {
                    float t0 = v0 + bias[cb], t1 = v1 + bias[cb + 1];
                    v0 = 0.5f * t0 * (1.0f + erff(t0 * 0.70710678118654752f));
                    v1 = 0.5f * t1 * (1.0f + erff(t1 * 0.70710678118654752f));
                    __half2 hv = __floats2half2_rn(v0, v1);
                    *(__half2*)((__half*)Cmat + (size_t)m * N + cb) = hv;
                } else {
                    float2 ov = { v0, v1 };
                    *(float2*)((float*)Cmat + (size_t)m * N + cb) = ov;
                }
            }
        }
    }
}

// ---------------- LayerNorm: one warp per token, fp16 out ----------------
__global__ void ln_kernel(const float* __restrict__ x, const float* __restrict__ g,
                          const float* __restrict__ b, __half* __restrict__ out) {
    const int warp = (blockIdx.x * 256 + threadIdx.x) >> 5;
    const int lane = threadIdx.x & 31;
    const float4* row = (const float4*)(x + (size_t)warp * CC);
    float4 v[4];
    float s = 0.f, q = 0.f;
#pragma unroll
    for (int i = 0; i < 4; i++) {
        v[i] = row[lane + 32 * i];
        s += v[i].x + v[i].y + v[i].z + v[i].w;
        q += v[i].x * v[i].x + v[i].y * v[i].y + v[i].z * v[i].z + v[i].w * v[i].w;
    }
#pragma unroll
    for (int o = 16; o; o >>= 1) {
        s += __shfl_xor_sync(0xFFFFFFFFu, s, o);
        q += __shfl_xor_sync(0xFFFFFFFFu, q, o);
    }
    const float mu  = s * (1.0f / CC);
    const float var = fmaxf(q * (1.0f / CC) - mu * mu, 0.0f);
    const float r   = rsqrtf(var + 1e-5f);

    __half* orow = out + (size_t)warp * CC;
    const float4* gg = (const float4*)g;
    const float4* bb = (const float4*)b;
#pragma unroll
    for (int i = 0; i < 4; i++) {
        float4 gv = gg[lane + 32 * i], bv = bb[lane + 32 * i];
        float o0 = (v[i].x - mu) * r * gv.x + bv.x;
        float o1 = (v[i].y - mu) * r * gv.y + bv.y;
        float o2 = (v[i].z - mu) * r * gv.z + bv.z;
        float o3 = (v[i].w - mu) * r * gv.w + bv.w;
        __half2 a = __floats2half2_rn(o0, o1);
        __half2 c = __floats2half2_rn(o2, o3);
        *(uint2*)(orow + (lane + 32 * i) * 4) = make_uint2(h2_u32(a), h2_u32(c));
    }
}

// ---------------- Attention: fp32 compute, fp16 out ----------------
__global__ void __launch_bounds__(256, 1)
attn_kernel(const float* __restrict__ qkv, __half* __restrict__ o) {
    __shared__ float Ks[64 * 64];
    __shared__ float Vs[64 * 64];
    const int head = blockIdx.x;
    const int seqb = blockIdx.y * SEQ;
    const int tid  = threadIdx.x;
    const int tq   = seqb + tid;

    u64 q2[32], o2[32];
    {
        const float4* qp = (const float4*)(qkv + (size_t)tq * C3 + head * HDIM);
#pragma unroll
        for (int t = 0; t < 16; t++) {
            float4 v = qp[t];
            q2[2 * t]     = pack2(v.x * 0.125f, v.y * 0.125f);
            q2[2 * t + 1] = pack2(v.z * 0.125f, v.w * 0.125f);
            o2[2 * t] = 0ull; o2[2 * t + 1] = 0ull;
        }
    }
    float mx = -1e30f, sm = 0.f;

    for (int ck = 0; ck < 4; ++ck) {
        __syncthreads();
#pragma unroll
        for (int it = 0; it < 4; ++it) {
            const int idx = it * 256 + tid;
            const int r = idx >> 4, c4 = idx & 15;
            const float* base = qkv + (size_t)(seqb + ck * 64 + r) * C3 + head * HDIM + c4 * 4;
            ((float4*)Ks)[idx] = *(const float4*)(base + 512);
            ((float4*)Vs)[idx] = *(const float4*)(base + 1024);
        }
        __syncthreads();

        for (int m = 0; m < 64; m++) {
            const u64* K2 = (const u64*)(Ks + m * 64);
            u64 s4[4] = { 0ull, 0ull, 0ull, 0ull };
#pragma unroll
            for (int j = 0; j < 32; j += 4) {
                s4[0] = fma2(q2[j + 0], K2[j + 0], s4[0]);
                s4[1] = fma2(q2[j + 1], K2[j + 1], s4[1]);
                s4[2] = fma2(q2[j + 2], K2[j + 2], s4[2]);
                s4[3] = fma2(q2[j + 3], K2[j + 3], s4[3]);
            }
            float2 p0 = unpack2(s4[0]), p1 = unpack2(s4[1]);
            float2 p2 = unpack2(s4[2]), p3 = unpack2(s4[3]);
            const float s = ((p0.x + p0.y) + (p1.x + p1.y)) + ((p2.x + p2.y) + (p3.x + p3.y));

            const float mn   = fmaxf(mx, s);
            const float corr = __expf(mx - mn);
            const float p    = __expf(s - mn);
            sm = sm * corr + p;
            mx = mn;

            const u64 cd = pack2(corr, corr);
            const u64 pd = pack2(p, p);
            const u64* V2 = (const u64*)(Vs + m * 64);
#pragma unroll
            for (int j = 0; j < 32; j++)
                o2[j] = fma2(o2[j], cd, mul2(pd, V2[j]));
        }
    }

    const float inv = 1.0f / sm;
    __half* op = o + (size_t)tq * CC + head * HDIM;
#pragma unroll
    for (int t = 0; t < 16; t++) {
        float2 a = unpack2(o2[2 * t]);
        float2 b = unpack2(o2[2 * t + 1]);
        __half2 h0 = __floats2half2_rn(a.x * inv, a.y * inv);
        __half2 h1 = __floats2half2_rn(b.x * inv, b.y * inv);
        *(uint2*)(op + t * 4) = make_uint2(h2_u32(h0), h2_u32(h1));
    }
}

// ---------------- launcher ----------------
extern "C" void kernel_launch(void* const* d_in, const int* in_sizes, int n_in,
                              void* d_out, int out_size) {
    const float* x     = (const float*)d_in[0];
    const float* ln1g  = (const float*)d_in[1];
    const float* ln1b  = (const float*)d_in[2];
    const float* wqkv  = (const float*)d_in[3];
    const float* wproj = (const float*)d_in[4];
    const float* bproj = (const float*)d_in[5];
    const float* ln2g  = (const float*)d_in[6];
    const float* ln2b  = (const float*)d_in[7];
    const float* w1    = (const float*)d_in[8];
    const float* b1    = (const float*)d_in[9];
    const float* w2    = (const float*)d_in[10];
    const float* b2    = (const float*)d_in[11];
    float* out = (float*)d_out;

    __half *h1h, *oh, *h2h, *ffh, *wqkvh, *wprojh, *w1h, *w2h;
    float *qkv, *x1;
    cudaGetSymbolAddress((void**)&h1h,   g_h1h);
    cudaGetSymbolAddress((void**)&qkv,   g_qkv);
    cudaGetSymbolAddress((void**)&oh,    g_oh);
    cudaGetSymbolAddress((void**)&x1,    g_x1);
    cudaGetSymbolAddress((void**)&h2h,   g_h2h);
    cudaGetSymbolAddress((void**)&ffh,   g_ffh);
    cudaGetSymbolAddress((void**)&wqkvh, g_wqkvh);
    cudaGetSymbolAddress((void**)&wprojh,g_wprojh);
    cudaGetSymbolAddress((void**)&w1h,   g_w1h);
    cudaGetSymbolAddress((void**)&w2h,   g_w2h);

    cudaFuncSetAttribute(gemm_mma<0>, cudaFuncAttributeMaxDynamicSharedMemorySize, GEMM_SMEM);
    cudaFuncSetAttribute(gemm_mma<1>, cudaFuncAttributeMaxDynamicSharedMemorySize, GEMM_SMEM);
    cudaFuncSetAttribute(gemm_mma<2>, cudaFuncAttributeMaxDynamicSharedMemorySize, GEMM_SMEM);

    // 0) weight fp32 -> fp16 once
    cvt_h_kernel<<<(C3 * CC) / 1024, 256>>>(wqkv, wqkvh);
    cvt_h_kernel<<<(CC * CC) / 1024, 256>>>(wproj, wprojh);
    cvt_h_kernel<<<(HID * CC) / 1024, 256>>>(w1, w1h);
    cvt_h_kernel<<<(CC * HID) / 1024, 256>>>(w2, w2h);

    // 1) LN1 (fp16 out)
    ln_kernel<<<TT / 8, 256>>>(x, ln1g, ln1b, h1h);
    // 2) QKV = h1 @ w_qkv^T (fp32 out)
    gemm_mma<0><<<dim3(C3 / 128, TT / 128), NTHR, GEMM_SMEM>>>(h1h, wqkvh, qkv, nullptr, nullptr, TT, C3, CC);
    // 3) attention (fp16 out)
    attn_kernel<<<dim3(NHEAD, NSEQ), 256>>>(qkv, oh);
    // 4) x1 = x + o @ w_proj^T + b_proj (fp32 out)
    gemm_mma<1><<<dim3(CC / 128, TT / 128), NTHR, GEMM_SMEM>>>(oh, wprojh, x1, bproj, x, TT, CC, CC);
    // 5) LN2 (fp16 out)
    ln_kernel<<<TT / 8, 256>>>(x1, ln2g, ln2b, h2h);
    // 6) ff = gelu(h2 @ w1^T + b1) (fp16 out)
    gemm_mma<2><<<dim3(HID / 128, TT / 128), NTHR, GEMM_SMEM>>>(h2h, w1h, ffh, b1, nullptr, TT, HID, CC);
    // 7) out = x1 + ff @ w2^T + b2 (fp32 out)
    gemm_mma<1><<<dim3(CC / 128, TT / 128), NTHR, GEMM_SMEM>>>(ffh, w2h, out, b2, x1, TT, CC, HID);
}

// round 16
// speedup vs baseline: 2.5678x; 1.5149x over previous
#include <cuda_runtime.h>
#include <cuda_fp16.h>
#include <math.h>
#include <stdint.h>

// ---------------- problem constants ----------------
#define TT    16384
#define CC    512
#define C3    1536
#define HID   2048
#define NHEAD 8
#define HDIM  64
#define SEQ   256
#define NSEQ  64

typedef unsigned long long u64;

// ---------------- scratch ----------------
__device__ __half g_h1h [(size_t)TT * CC];    // ln1 out (fp16)
__device__ __half g_qkvh[(size_t)TT * C3];    // qkv (fp16: TC attention input)
__device__ __half g_oh  [(size_t)TT * CC];    // attention out (fp16)
__device__ float  g_x1  [(size_t)TT * CC];    // x + proj (fp32 residual)
__device__ __half g_h2h [(size_t)TT * CC];    // ln2 out (fp16)
__device__ __half g_ffh [(size_t)TT * HID];   // gelu out (fp16)
__device__ __half g_wqkvh [(size_t)C3 * CC];
__device__ __half g_wprojh[(size_t)CC * CC];
__device__ __half g_w1h   [(size_t)HID * CC];
__device__ __half g_w2h   [(size_t)CC * HID];

// ---------------- mma.sync / ldmatrix / cp.async helpers (sm_80+ PTX) -------
static __device__ __forceinline__ uint32_t smem_u32(const void* p) {
    uint32_t a;
    asm("{ .reg .u64 t; cvta.to.shared.u64 t, %1; cvt.u32.u64 %0, t; }" : "=r"(a) : "l"(p));
    return a;
}
static __device__ __forceinline__ void ldmat_x4(uint32_t* r, uint32_t addr) {
    asm volatile("ldmatrix.sync.aligned.m8n8.x4.shared.b16 {%0,%1,%2,%3}, [%4];"
        : "=r"(r[0]), "=r"(r[1]), "=r"(r[2]), "=r"(r[3]) : "r"(addr));
}
static __device__ __forceinline__ void ldmat_x2(uint32_t* r, uint32_t addr) {
    asm volatile("ldmatrix.sync.aligned.m8n8.x2.shared.b16 {%0,%1}, [%2];"
        : "=r"(r[0]), "=r"(r[1]) : "r"(addr));
}
static __device__ __forceinline__ void ldmat_x2_trans(uint32_t* r, uint32_t addr) {
    asm volatile("ldmatrix.sync.aligned.m8n8.x2.trans.shared.b16 {%0,%1}, [%2];"
        : "=r"(r[0]), "=r"(r[1]) : "r"(addr));
}
static __device__ __forceinline__ void mma_f16(float* d, const uint32_t* a, const uint32_t* b) {
    asm volatile("mma.sync.aligned.m16n8k16.row.col.f32.f16.f16.f32 "
        "{%0,%1,%2,%3},{%4,%5,%6,%7},{%8,%9},{%0,%1,%2,%3};"
        : "+f"(d[0]), "+f"(d[1]), "+f"(d[2]), "+f"(d[3])
        : "r"(a[0]), "r"(a[1]), "r"(a[2]), "r"(a[3]), "r"(b[0]), "r"(b[1]));
}
static __device__ __forceinline__ uint32_t h2_u32(__half2 h) {
    union { __half2 h; uint32_t u; } c; c.h = h; return c.u;
}
static __device__ __forceinline__ void cp_async16(uint32_t dst, const void* src) {
    asm volatile("cp.async.cg.shared.global [%0], [%1], 16;" :: "r"(dst), "l"(src));
}
#define CP_COMMIT() asm volatile("cp.async.commit_group;" ::: "memory")
#define CP_WAIT0()  asm volatile("cp.async.wait_group 0;" ::: "memory")

// ---------------- weight fp32 -> fp16 prep ----------------
__global__ void cvt_h_kernel(const float* __restrict__ in, __half* __restrict__ out) {
    const int i = (blockIdx.x * 256 + threadIdx.x) * 4;
    float4 v = *(const float4*)(in + i);
    __half2 a = __floats2half2_rn(v.x, v.y);
    __half2 b = __floats2half2_rn(v.z, v.w);
    *(uint2*)(out + i) = make_uint2(h2_u32(a), h2_u32(b));
}

// ---------------- fp16 GEMM (NT): C = A[M,K] * B[N,K]^T, cp.async staged ----
#define NTHR   512
#define KCH    64
#define ASTR   144
#define TILE_B (128 * ASTR)
#define BUF_B  (2 * TILE_B)
#define GEMM_SMEM (2 * BUF_B)            // 73728 B

// EPI: 0 = fp16 plain out; 1 = fp32 out +bias+res; 2 = fp16 out gelu(+bias)
template <int EPI>
__global__ void __launch_bounds__(NTHR, 1)
gemm_mma(const __half* __restrict__ A, const __half* __restrict__ B,
         void* __restrict__ Cmat, const float* __restrict__ bias,
         const float* __restrict__ res, int M, int N, int K) {
    extern __shared__ char smem[];
    const uint32_t sb = smem_u32(smem);
    const int tid  = threadIdx.x;
    const int wid  = tid >> 5;
    const int lane = tid & 31;
    const int bm = blockIdx.y << 7;
    const int bn = blockIdx.x << 7;

    const int wm = (wid & 3) * 32;
    const int wn = (wid >> 2) * 32;

    const uint32_t aro = (uint32_t)(lane & 15) * ASTR + (uint32_t)(lane >> 4) * 16u;
    const uint32_t bro = (uint32_t)(lane & 7) * ASTR + (uint32_t)((lane >> 3) & 1) * 16u;

    const int r0 = tid >> 3,          c80 = (tid & 7) << 3;
    const int r1 = (NTHR + tid) >> 3, c81 = ((NTHR + tid) & 7) << 3;

    float acc[2][4][4];
#pragma unroll
    for (int i = 0; i < 2; i++)
#pragma unroll
        for (int j = 0; j < 4; j++)
#pragma unroll
            for (int e = 0; e < 4; e++) acc[i][j][e] = 0.f;

    const int NC = K / KCH;

    {
        const uint32_t bp = sb;
        cp_async16(bp + (uint32_t)r0 * ASTR + (uint32_t)c80 * 2u, A + (size_t)(bm + r0) * K + c80);
        cp_async16(bp + (uint32_t)r1 * ASTR + (uint32_t)c81 * 2u, A + (size_t)(bm + r1) * K + c81);
        cp_async16(bp + TILE_B + (uint32_t)r0 * ASTR + (uint32_t)c80 * 2u, B + (size_t)(bn + r0) * K + c80);
        cp_async16(bp + TILE_B + (uint32_t)r1 * ASTR + (uint32_t)c81 * 2u, B + (size_t)(bn + r1) * K + c81);
        CP_COMMIT();
    }

    for (int c = 0; c < NC; ++c) {
        CP_WAIT0();
        __syncthreads();

        if (c + 1 < NC) {
            const uint32_t bp = sb + ((c + 1) & 1) * BUF_B;
            const int kb = (c + 1) * KCH;
            cp_async16(bp + (uint32_t)r0 * ASTR + (uint32_t)c80 * 2u, A + (size_t)(bm + r0) * K + kb + c80);
            cp_async16(bp + (uint32_t)r1 * ASTR + (uint32_t)c81 * 2u, A + (size_t)(bm + r1) * K + kb + c81);
            cp_async16(bp + TILE_B + (uint32_t)r0 * ASTR + (uint32_t)c80 * 2u, B + (size_t)(bn + r0) * K + kb + c80);
            cp_async16(bp + TILE_B + (uint32_t)r1 * ASTR + (uint32_t)c81 * 2u, B + (size_t)(bn + r1) * K + kb + c81);
            CP_COMMIT();
        }

        const uint32_t bufb = sb + (c & 1) * BUF_B;
        const uint32_t aT = bufb, bT = bufb + TILE_B;

#pragma unroll
        for (int ks = 0; ks < 4; ks++) {
            const uint32_t kso = (uint32_t)ks * 32u;
            uint32_t bh[4][2];
#pragma unroll
            for (int nt = 0; nt < 4; nt++) {
                const uint32_t ro = (uint32_t)(wn + nt * 8) * ASTR + kso + bro;
                ldmat_x2(bh[nt], bT + ro);
            }
            uint32_t ah[2][4];
#pragma unroll
            for (int mt = 0; mt < 2; mt++) {
                const uint32_t ro = (uint32_t)(wm + mt * 16) * ASTR + kso + aro;
                ldmat_x4(ah[mt], aT + ro);
            }
#pragma unroll
            for (int mt = 0; mt < 2; mt++)
#pragma unroll
                for (int nt = 0; nt < 4; nt++)
                    mma_f16(acc[mt][nt], ah[mt], bh[nt]);
        }
    }

    const int g   = lane >> 2;
    const int tig = lane & 3;
#pragma unroll
    for (int mt = 0; mt < 2; mt++) {
#pragma unroll
        for (int half = 0; half < 2; half++) {
            const int m = bm + wm + mt * 16 + g + 8 * half;
            const float* rrow = (EPI == 1) ? (res + (size_t)m * N) : nullptr;
#pragma unroll
            for (int nt = 0; nt < 4; nt++) {
                const int cb = bn + wn + nt * 8 + 2 * tig;
                float v0 = acc[mt][nt][2 * half];
                float v1 = acc[mt][nt][2 * half + 1];
                if (EPI == 1) {
                    float2 rv = *(const float2*)(rrow + cb);
                    v0 += bias[cb] + rv.x;
                    v1 += bias[cb + 1] + rv.y;
                    float2 ov = { v0, v1 };
                    *(float2*)((float*)Cmat + (size_t)m * N + cb) = ov;
                } else if (EPI == 2) {
                    float t0 = v0 + bias[cb], t1 = v1 + bias[cb + 1];
                    v0 = 0.5f * t0 * (1.0f + erff(t0 * 0.70710678118654752f));
                    v1 = 0.5f * t1 * (1.0f + erff(t1 * 0.70710678118654752f));
                    __half2 hv = __floats2half2_rn(v0, v1);
                    *(__half2*)((__half*)Cmat + (size_t)m * N + cb) = hv;
                } else {
                    __half2 hv = __floats2half2_rn(v0, v1);
                    *(__half2*)((__half*)Cmat + (size_t)m * N + cb) = hv;
                }
            }
        }
    }
}

// ---------------- LayerNorm: one warp per token, fp16 out ----------------
__global__ void ln_kernel(const float* __restrict__ x, const float* __restrict__ g,
                          const float* __restrict__ b, __half* __restrict__ out) {
    const int warp = (blockIdx.x * 256 + threadIdx.x) >> 5;
    const int lane = threadIdx.x & 31;
    const float4* row = (const float4*)(x + (size_t)warp * CC);
    float4 v[4];
    float s = 0.f, q = 0.f;
#pragma unroll
    for (int i = 0; i < 4; i++) {
        v[i] = row[lane + 32 * i];
        s += v[i].x + v[i].y + v[i].z + v[i].w;
        q += v[i].x * v[i].x + v[i].y * v[i].y + v[i].z * v[i].z + v[i].w * v[i].w;
    }
#pragma unroll
    for (int o = 16; o; o >>= 1) {
        s += __shfl_xor_sync(0xFFFFFFFFu, s, o);
        q += __shfl_xor_sync(0xFFFFFFFFu, q, o);
    }
    const float mu  = s * (1.0f / CC);
    const float var = fmaxf(q * (1.0f / CC) - mu * mu, 0.0f);
    const float r   = rsqrtf(var + 1e-5f);

    __half* orow = out + (size_t)warp * CC;
    const float4* gg = (const float4*)g;
    const float4* bb = (const float4*)b;
#pragma unroll
    for (int i = 0; i < 4; i++) {
        float4 gv = gg[lane + 32 * i], bv = bb[lane + 32 * i];
        float o0 = (v[i].x - mu) * r * gv.x + bv.x;
        float o1 = (v[i].y - mu) * r * gv.y + bv.y;
        float o2 = (v[i].z - mu) * r * gv.z + bv.z;
        float o3 = (v[i].w - mu) * r * gv.w + bv.w;
        __half2 a = __floats2half2_rn(o0, o1);
        __half2 c = __floats2half2_rn(o2, o3);
        *(uint2*)(orow + (lane + 32 * i) * 4) = make_uint2(h2_u32(a), h2_u32(c));
    }
}

// ---------------- Flash attention on tensor cores ----------------
// Block: (head, 128-query tile). 8 warps x 16 query rows. fp16 Q/K/V from qkv,
// fp32 accum + fp32 online softmax, fp16 output.
#define AQ_STR 144                       // 64 halves + 8 pad (bytes)
#define AQ_B   (128 * AQ_STR)            // Q tile: 18432 B
#define AK_B   (64 * AQ_STR)             // K or V chunk: 9216 B
#define ATTN_SMEM (AQ_B + 4 * AK_B)      // 55296 B

__global__ void __launch_bounds__(256, 1)
attn_kernel(const __half* __restrict__ qkv, __half* __restrict__ o) {
    extern __shared__ char smem[];
    const uint32_t sb = smem_u32(smem);
    const int head = blockIdx.x;
    const int qb   = blockIdx.y * 128;               // query base token
    const int kb0  = (blockIdx.y >> 1) * SEQ;        // key base token (seq start)
    const int tid  = threadIdx.x;
    const int wid  = tid >> 5;
    const int lane = tid & 31;
    const int wq   = wid * 16;                       // warp query offset in tile

    const uint32_t aro = (uint32_t)(lane & 15) * AQ_STR + (uint32_t)(lane >> 4) * 16u;
    const uint32_t bro = (uint32_t)(lane & 7) * AQ_STR + (uint32_t)((lane >> 3) & 1) * 16u;

    const uint32_t Qs = sb;
    const uint32_t Ks[2] = { sb + AQ_B,            sb + AQ_B + 2 * AK_B };
    const uint32_t Vs[2] = { sb + AQ_B + AK_B,     sb + AQ_B + 3 * AK_B };

    // ---- prologue: stage Q (128x64) + K/V chunk 0 (64x64 each) ----
    {
#pragma unroll
        for (int i = 0; i < 4; i++) {                 // Q: 1024 granules
            int f = i * 256 + tid;
            int row = f >> 3, c8 = (f & 7) << 3;
            cp_async16(Qs + (uint32_t)row * AQ_STR + (uint32_t)c8 * 2u,
                       qkv + (size_t)(qb + row) * C3 + head * HDIM + c8);
        }
#pragma unroll
        for (int i = 0; i < 2; i++) {                 // K chunk 0: 512 granules
            int f = i * 256 + tid;
            int row = f >> 3, c8 = (f & 7) << 3;
            cp_async16(Ks[0] + (uint32_t)row * AQ_STR + (uint32_t)c8 * 2u,
                       qkv + (size_t)(kb0 + row) * C3 + head * HDIM + 512 + c8);
        }
#pragma unroll
        for (int i = 0; i < 2; i++) {                 // V chunk 0
            int f = i * 256 + tid;
            int row = f >> 3, c8 = (f & 7) << 3;
            cp_async16(Vs[0] + (uint32_t)row * AQ_STR + (uint32_t)c8 * 2u,
                       qkv + (size_t)(kb0 + row) * C3 + head * HDIM + 1024 + c8);
        }
        CP_COMMIT();
    }
    CP_WAIT0();
    __syncthreads();

    // ---- load Q fragments (kept in registers for all chunks) ----
    uint32_t aq[4][4];
#pragma unroll
    for (int ks = 0; ks < 4; ks++)
        ldmat_x4(aq[ks], Qs + (uint32_t)wq * AQ_STR + (uint32_t)ks * 32u + aro);

    float m0 = -1e30f, m1 = -1e30f, l0 = 0.f, l1 = 0.f;
    float ao[8][4];
#pragma unroll
    for (int nd = 0; nd < 8; nd++)
#pragma unroll
        for (int e = 0; e < 4; e++) ao[nd][e] = 0.f;

    for (int c = 0; c < 4; ++c) {
        // issue prefetch of chunk c+1
        if (c + 1 < 4) {
            const int nb = (c + 1) & 1;
            const int kt = kb0 + (c + 1) * 64;
#pragma unroll
            for (int i = 0; i < 2; i++) {
                int f = i * 256 + tid;
                int row = f >> 3, c8 = (f & 7) << 3;
                cp_async16(Ks[nb] + (uint32_t)row * AQ_STR + (uint32_t)c8 * 2u,
                           qkv + (size_t)(kt + row) * C3 + head * HDIM + 512 + c8);
            }
#pragma unroll
            for (int i = 0; i < 2; i++) {
                int f = i * 256 + tid;
                int row = f >> 3, c8 = (f & 7) << 3;
                cp_async16(Vs[nb] + (uint32_t)row * AQ_STR + (uint32_t)c8 * 2u,
                           qkv + (size_t)(kt + row) * C3 + head * HDIM + 1024 + c8);
            }
            CP_COMMIT();
        }

        const uint32_t kT = Ks[c & 1], vT = Vs[c & 1];

        // ---- S = Q K^T (fp32 accum) ----
        float sc[8][4];
#pragma unroll
        for (int nt = 0; nt < 8; nt++)
#pragma unroll
            for (int e = 0; e < 4; e++) sc[nt][e] = 0.f;
#pragma unroll
        for (int ks = 0; ks < 4; ks++) {
            const uint32_t kso = (uint32_t)ks * 32u;
#pragma unroll
            for (int nt = 0; nt < 8; nt++) {
                uint32_t bk[2];
                ldmat_x2(bk, kT + (uint32_t)(nt * 8) * AQ_STR + kso + bro);
                mma_f16(sc[nt], aq[ks], bk);
            }
        }

        // ---- online softmax (rows g and g+8; quad = lanes sharing g) ----
        float mx0 = -1e30f, mx1 = -1e30f;
#pragma unroll
        for (int nt = 0; nt < 8; nt++) {
            mx0 = fmaxf(mx0, fmaxf(sc[nt][0], sc[nt][1]));
            mx1 = fmaxf(mx1, fmaxf(sc[nt][2], sc[nt][3]));
        }
        mx0 = fmaxf(mx0, __shfl_xor_sync(0xFFFFFFFFu, mx0, 1));
        mx0 = fmaxf(mx0, __shfl_xor_sync(0xFFFFFFFFu, mx0, 2));
        mx1 = fmaxf(mx1, __shfl_xor_sync(0xFFFFFFFFu, mx1, 1));
        mx1 = fmaxf(mx1, __shfl_xor_sync(0xFFFFFFFFu, mx1, 2));

        const float m0n = fmaxf(m0, mx0 * 0.125f);
        const float m1n = fmaxf(m1, mx1 * 0.125f);
        const float cr0 = __expf(m0 - m0n);
        const float cr1 = __expf(m1 - m1n);
        m0 = m0n; m1 = m1n;

        float s0 = 0.f, s1 = 0.f;
#pragma unroll
        for (int nt = 0; nt < 8; nt++) {
            sc[nt][0] = __expf(sc[nt][0] * 0.125f - m0n);
            sc[nt][1] = __expf(sc[nt][1] * 0.125f - m0n);
            sc[nt][2] = __expf(sc[nt][2] * 0.125f - m1n);
            sc[nt][3] = __expf(sc[nt][3] * 0.125f - m1n);
            s0 += sc[nt][0] + sc[nt][1];
            s1 += sc[nt][2] + sc[nt][3];
        }
        s0 += __shfl_xor_sync(0xFFFFFFFFu, s0, 1);
        s0 += __shfl_xor_sync(0xFFFFFFFFu, s0, 2);
        s1 += __shfl_xor_sync(0xFFFFFFFFu, s1, 1);
        s1 += __shfl_xor_sync(0xFFFFFFFFu, s1, 2);
        l0 = l0 * cr0 + s0;
        l1 = l1 * cr1 + s1;

#pragma unroll
        for (int nd = 0; nd < 8; nd++) {
            ao[nd][0] *= cr0; ao[nd][1] *= cr0;
            ao[nd][2] *= cr1; ao[nd][3] *= cr1;
        }

        // ---- P fp16 a-frags (two adjacent n8 S-frags -> one k16 a-frag) ----
        uint32_t ap[4][4];
#pragma unroll
        for (int kf = 0; kf < 4; kf++) {
            ap[kf][0] = h2_u32(__floats2half2_rn(sc[2 * kf][0],     sc[2 * kf][1]));
            ap[kf][1] = h2_u32(__floats2half2_rn(sc[2 * kf][2],     sc[2 * kf][3]));
            ap[kf][2] = h2_u32(__floats2half2_rn(sc[2 * kf + 1][0], sc[2 * kf + 1][1]));
            ap[kf][3] = h2_u32(__floats2half2_rn(sc[2 * kf + 1][2], sc[2 * kf + 1][3]));
        }

        // ---- O += P V  (V^T b-frags via ldmatrix.trans on row-major V) ----
#pragma unroll
        for (int kf = 0; kf < 4; kf++) {
            const uint32_t vrow = vT + (uint32_t)(kf * 16 + (lane & 15)) * AQ_STR;
#pragma unroll
            for (int nd = 0; nd < 8; nd++) {
                uint32_t bv[2];
                ldmat_x2_trans(bv, vrow + (uint32_t)nd * 16u);
                mma_f16(ao[nd], ap[kf], bv);
            }
        }

        if (c + 1 < 4) {
            CP_WAIT0();
            __syncthreads();
        }
    }

    // ---- write O (fp16) ----
    const int g   = lane >> 2;
    const int tig = lane & 3;
    const float i0 = 1.0f / l0, i1 = 1.0f / l1;
    const int r0 = qb + wq + g, r1 = r0 + 8;
#pragma unroll
    for (int nd = 0; nd < 8; nd++) {
        const int col = head * HDIM + nd * 8 + 2 * tig;
        __half2 h0 = __floats2half2_rn(ao[nd][0] * i0, ao[nd][1] * i0);
        __half2 h1 = __floats2half2_rn(ao[nd][2] * i1, ao[nd][3] * i1);
        *(__half2*)(o + (size_t)r0 * CC + col) = h0;
        *(__half2*)(o + (size_t)r1 * CC + col) = h1;
    }
}

// ---------------- launcher ----------------
extern "C" void kernel_launch(void* const* d_in, const int* in_sizes, int n_in,
                              void* d_out, int out_size) {
    const float* x     = (const float*)d_in[0];
    const float* ln1g  = (const float*)d_in[1];
    const float* ln1b  = (const float*)d_in[2];
    const float* wqkv  = (const float*)d_in[3];
    const float* wproj = (const float*)d_in[4];
    const float* bproj = (const float*)d_in[5];
    const float* ln2g  = (const float*)d_in[6];
    const float* ln2b  = (const float*)d_in[7];
    const float* w1    = (const float*)d_in[8];
    const float* b1    = (const float*)d_in[9];
    const float* w2    = (const float*)d_in[10];
    const float* b2    = (const float*)d_in[11];
    float* out = (float*)d_out;

    __half *h1h, *qkvh, *oh, *h2h, *ffh, *wqkvh, *wprojh, *w1h, *w2h;
    float *x1;
    cudaGetSymbolAddress((void**)&h1h,   g_h1h);
    cudaGetSymbolAddress((void**)&qkvh,  g_qkvh);
    cudaGetSymbolAddress((void**)&oh,    g_oh);
    cudaGetSymbolAddress((void**)&x1,    g_x1);
    cudaGetSymbolAddress((void**)&h2h,   g_h2h);
    cudaGetSymbolAddress((void**)&ffh,   g_ffh);
    cudaGetSymbolAddress((void**)&wqkvh, g_wqkvh);
    cudaGetSymbolAddress((void**)&wprojh,g_wprojh);
    cudaGetSymbolAddress((void**)&w1h,   g_w1h);
    cudaGetSymbolAddress((void**)&w2h,   g_w2h);

    cudaFuncSetAttribute(gemm_mma<0>, cudaFuncAttributeMaxDynamicSharedMemorySize, GEMM_SMEM);
    cudaFuncSetAttribute(gemm_mma<1>, cudaFuncAttributeMaxDynamicSharedMemorySize, GEMM_SMEM);
    cudaFuncSetAttribute(gemm_mma<2>, cudaFuncAttributeMaxDynamicSharedMemorySize, GEMM_SMEM);
    cudaFuncSetAttribute(attn_kernel, cudaFuncAttributeMaxDynamicSharedMemorySize, ATTN_SMEM);

    // 0) weight fp32 -> fp16 once
    cvt_h_kernel<<<(C3 * CC) / 1024, 256>>>(wqkv, wqkvh);
    cvt_h_kernel<<<(CC * CC) / 1024, 256>>>(wproj, wprojh);
    cvt_h_kernel<<<(HID * CC) / 1024, 256>>>(w1, w1h);
    cvt_h_kernel<<<(CC * HID) / 1024, 256>>>(w2, w2h);

    // 1) LN1 (fp16 out)
    ln_kernel<<<TT / 8, 256>>>(x, ln1g, ln1b, h1h);
    // 2) QKV = h1 @ w_qkv^T (fp16 out)
    gemm_mma<0><<<dim3(C3 / 128, TT / 128), NTHR, GEMM_SMEM>>>(h1h, wqkvh, qkvh, nullptr, nullptr, TT, C3, CC);
    // 3) TC flash attention (fp16 out)
    attn_kernel<<<dim3(NHEAD, TT / 128), 256, ATTN_SMEM>>>(qkvh, oh);
    // 4) x1 = x + o @ w_proj^T + b_proj (fp32 out)
    gemm_mma<1><<<dim3(CC / 128, TT / 128), NTHR, GEMM_SMEM>>>(oh, wprojh, x1, bproj, x, TT, CC, CC);
    // 5) LN2 (fp16 out)
    ln_kernel<<<TT / 8, 256>>>(x1, ln2g, ln2b, h2h);
    // 6) ff = gelu(h2 @ w1^T + b1) (fp16 out)
    gemm_mma<2><<<dim3(HID / 128, TT / 128), NTHR, GEMM_SMEM>>>(h2h, w1h, ffh, b1, nullptr, TT, HID, CC);
    // 7) out = x1 + ff @ w2^T + b2 (fp32 out)
    gemm_mma<1><<<dim3(CC / 128, TT / 128), NTHR, GEMM_SMEM>>>(ffh, w2h, out, b2, x1, TT, CC, HID);
}